// round 7
// baseline (speedup 1.0000x reference)
#include <cuda_runtime.h>
#include <math.h>

// Problem constants
#define B_ 512
#define T_ 2048
#define H_ 128
#define E_ 256
#define V_ 34
#define NBLK 128
#define NTHR 512

// Output layout: (out[B,V], c[B,H], sh0[B,H], sh1[B,H], sc0[B,H], sc1[B,H], atten_vec[T])
#define OFF_OUT 0
#define OFF_C   (B_*V_)
#define OFF_SH0 (OFF_C   + B_*H_)
#define OFF_SH1 (OFF_SH0 + B_*H_)
#define OFF_SC0 (OFF_SH1 + B_*H_)
#define OFF_SC1 (OFF_SC0 + B_*H_)
#define OFF_ATT (OFF_SC1 + B_*H_)

// Scratch (__device__ globals; no allocations allowed)
__device__ float g_pre[B_*H_];
__device__ float g_mean[H_];
__device__ float g_var[H_];
__device__ unsigned g_cnt = 0;
__device__ unsigned g_gen = 0;

struct GemmBuf { float Xs[2][16][17]; float Ws[2][16][68]; };
struct AttnBuf { float sa[T_]; float4 sq[32]; float4 part[16][32]; float red[NTHR]; };
struct BnBuf   { float rs[NTHR]; float rq[NTHR]; };
struct FinBuf  { float sn[4][H_]; };
union Smem {
    GemmBuf gm[2];
    AttnBuf at;
    BnBuf   bn;
    FinBuf  fin;
};

__device__ __forceinline__ float sigm(float x) { return 1.f / (1.f + __expf(-x)); }

// Software grid barrier. All NBLK blocks resident (grid < SM count, 1 block/SM
// guaranteed). Sense-reversing via generation counter; gen snapshot taken
// BEFORE arrival so a release between snapshot and spin is impossible to miss.
__device__ __forceinline__ void grid_barrier() {
    __syncthreads();
    if (threadIdx.x == 0) {
        __threadfence();                               // publish this block's writes
        unsigned gen = *((volatile unsigned*)&g_gen);
        if (atomicAdd(&g_cnt, 1u) == NBLK - 1) {
            *((volatile unsigned*)&g_cnt) = 0;
            __threadfence();
            atomicAdd(&g_gen, 1u);                     // release
        } else {
            while (*((volatile unsigned*)&g_gen) == gen) { __nanosleep(64); }
        }
    }
    __syncthreads();
}

// ---------------------------------------------------------------------------
// One LSTM GEMM tile (16 batch rows x 16 h = 64 gate cols), run by one
// 256-thread worker (widx 0/1 inside the 512-thread block). Both workers
// execute identical sync sequences (same nt), so block-wide __syncthreads
// is safe. Epilogue applies bias + gate activations.
// ---------------------------------------------------------------------------
__device__ void lstm_tile(Smem& s, int widx, int wtid,
    const float* __restrict__ A, int ka,
    const float* __restrict__ Bp, int kb,
    const float* __restrict__ Cp, int kc,
    const float* __restrict__ Wih, int Kin,
    const float* __restrict__ Whh,
    const float* __restrict__ bih, const float* __restrict__ bhh,
    const float* __restrict__ c_prev,
    float* __restrict__ h_out, float* __restrict__ c_out,
    int m0, int h0)
{
    GemmBuf& g = s.gm[widx];
    const int tx = wtid & 15, ty = wtid >> 4;
    const int lkk = tx, lr = ty;
    const int K = ka + kb + kc;
    const int nt = K >> 4;

    int wn[4];
    #pragma unroll
    for (int p = 0; p < 4; p++) {
        int ccol = lr + p * 16;
        wn[p] = (ccol & 3) * H_ + h0 + (ccol >> 2);   // gate*H + h
    }
    {
        int k = lkk;
        float x0;
        if (k < ka)           x0 = __ldcg(&A[(m0+lr)*ka + k]);
        else if (k < ka + kb) x0 = __ldcg(&Bp[(m0+lr)*kb + k - ka]);
        else                  x0 = __ldcg(&Cp[(m0+lr)*kc + k - ka - kb]);
        g.Xs[0][lkk][lr] = x0;
        #pragma unroll
        for (int p = 0; p < 4; p++)
            g.Ws[0][lkk][lr + p*16] = (k < Kin) ? Wih[wn[p]*Kin + k] : Whh[wn[p]*H_ + k - Kin];
    }
    __syncthreads();

    float acc[4] = {};
    for (int it = 0; it < nt; it++) {
        const int cur = it & 1, nxt = cur ^ 1;
        float px0 = 0.f, pw[4] = {0.f,0.f,0.f,0.f};
        const bool more = (it + 1 < nt);
        if (more) {
            int k = (it + 1) * 16 + lkk;
            if (k < ka)           px0 = __ldcg(&A[(m0+lr)*ka + k]);
            else if (k < ka + kb) px0 = __ldcg(&Bp[(m0+lr)*kb + k - ka]);
            else                  px0 = __ldcg(&Cp[(m0+lr)*kc + k - ka - kb]);
            #pragma unroll
            for (int p = 0; p < 4; p++)
                pw[p] = (k < Kin) ? Wih[wn[p]*Kin + k] : Whh[wn[p]*H_ + k - Kin];
        }
        #pragma unroll
        for (int kk = 0; kk < 16; kk++) {
            float x0 = g.Xs[cur][kk][ty];
            float4 wv = *(const float4*)&g.Ws[cur][kk][tx*4];
            acc[0] = fmaf(x0, wv.x, acc[0]);
            acc[1] = fmaf(x0, wv.y, acc[1]);
            acc[2] = fmaf(x0, wv.z, acc[2]);
            acc[3] = fmaf(x0, wv.w, acc[3]);
        }
        if (more) {
            g.Xs[nxt][lkk][lr] = px0;
            #pragma unroll
            for (int p = 0; p < 4; p++) g.Ws[nxt][lkk][lr + p*16] = pw[p];
            __syncthreads();
        }
    }

    const int h = h0 + tx, m = m0 + ty;
    float ig = sigm(acc[0] + bih[h]         + bhh[h]);
    float fg = sigm(acc[1] + bih[H_ + h]    + bhh[H_ + h]);
    float gg = tanhf(acc[2] + bih[2*H_ + h] + bhh[2*H_ + h]);
    float og = sigm(acc[3] + bih[3*H_ + h]  + bhh[3*H_ + h]);
    float cn = fg * c_prev[m*H_ + h] + ig * gg;
    c_out[m*H_ + h] = cn;
    h_out[m*H_ + h] = og * tanhf(cn);
}

// ---------------------------------------------------------------------------
// One head GEMM tile (16 rows x 64 cols), K=256 over [sh1|c] and [W1|W2].
// ---------------------------------------------------------------------------
__device__ void head_tile(Smem& s, int widx, int wtid,
    const float* __restrict__ sh1, const float* __restrict__ cvec,
    const float* __restrict__ W1, const float* __restrict__ W2,
    const float* __restrict__ b1, const float* __restrict__ b2,
    int m0, int n0)
{
    GemmBuf& g = s.gm[widx];
    const int tx = wtid & 15, ty = wtid >> 4;
    const int lkk = tx, lr = ty;
    const int nt = 16;  // K=256

    {
        int k = lkk;
        g.Xs[0][lkk][lr] = __ldcg(&sh1[(m0+lr)*H_ + k]);
        #pragma unroll
        for (int p = 0; p < 4; p++)
            g.Ws[0][lkk][lr + p*16] = W1[(n0 + lr + p*16)*H_ + k];
    }
    __syncthreads();

    float acc[4] = {};
    for (int it = 0; it < nt; it++) {
        const int cur = it & 1, nxt = cur ^ 1;
        float px0 = 0.f, pw[4] = {0.f,0.f,0.f,0.f};
        const bool more = (it + 1 < nt);
        if (more) {
            int k = (it + 1) * 16 + lkk;
            if (k < H_) {
                px0 = __ldcg(&sh1[(m0+lr)*H_ + k]);
                #pragma unroll
                for (int p = 0; p < 4; p++) pw[p] = W1[(n0+lr+p*16)*H_ + k];
            } else {
                int k2 = k - H_;
                px0 = __ldcg(&cvec[(m0+lr)*H_ + k2]);
                #pragma unroll
                for (int p = 0; p < 4; p++) pw[p] = W2[(n0+lr+p*16)*H_ + k2];
            }
        }
        #pragma unroll
        for (int kk = 0; kk < 16; kk++) {
            float x0 = g.Xs[cur][kk][ty];
            float4 wv = *(const float4*)&g.Ws[cur][kk][tx*4];
            acc[0] = fmaf(x0, wv.x, acc[0]);
            acc[1] = fmaf(x0, wv.y, acc[1]);
            acc[2] = fmaf(x0, wv.z, acc[2]);
            acc[3] = fmaf(x0, wv.w, acc[3]);
        }
        if (more) {
            g.Xs[nxt][lkk][lr] = px0;
            #pragma unroll
            for (int p = 0; p < 4; p++) g.Ws[nxt][lkk][lr + p*16] = pw[p];
            __syncthreads();
        }
    }
    const int n = n0 + tx*4;
    const int m = m0 + ty;
    #pragma unroll
    for (int j = 0; j < 4; j++)
        g_pre[(size_t)m*H_ + n + j] = acc[j] + b1[n+j] + b2[n+j];
}

// ---------------------------------------------------------------------------
// The whole model as one persistent kernel. grid = 128 blocks x 512 threads.
// ---------------------------------------------------------------------------
__global__ void __launch_bounds__(NTHR, 1) k_mega(
    const float* __restrict__ hk, const float* __restrict__ hv,
    const float* __restrict__ y_1, const float* __restrict__ c_1,
    const float* __restrict__ sh_1, const float* __restrict__ sc_1,
    const float* __restrict__ mask,
    const float* __restrict__ W_ih0, const float* __restrict__ W_hh0,
    const float* __restrict__ b_ih0, const float* __restrict__ b_hh0,
    const float* __restrict__ W_ih1, const float* __restrict__ W_hh1,
    const float* __restrict__ b_ih1, const float* __restrict__ b_hh1,
    const float* __restrict__ W1, const float* __restrict__ b1,
    const float* __restrict__ W2, const float* __restrict__ b2,
    const float* __restrict__ W3, const float* __restrict__ b3,
    const float* __restrict__ gamma, const float* __restrict__ beta,
    float* __restrict__ d_out)
{
    __shared__ Smem s;
    const int tid = threadIdx.x;
    const int bid = blockIdx.x;
    const int widx = tid >> 8;         // 0/1: 256-thread worker
    const int wtid = tid & 255;
    const int w = bid * 2 + widx;      // global worker id 0..255

    float* sh0_o = d_out + OFF_SH0;
    float* sh1_o = d_out + OFF_SH1;
    float* sc0_o = d_out + OFF_SC0;
    float* sc1_o = d_out + OFF_SC1;
    float* c_o   = d_out + OFF_C;
    float* att_o = d_out + OFF_ATT;

    // ---- Phase 1: LSTM0. 256 tiles (32 row-tiles x 8 h-tiles).
    lstm_tile(s, widx, wtid,
              y_1, E_, c_1, H_, sh_1, H_,
              W_ih0, E_ + H_, W_hh0, b_ih0, b_hh0, sc_1,
              sh0_o, sc0_o, (w >> 3) * 16, (w & 7) * 16);
    grid_barrier();

    // ---- Phase 2: LSTM1. K=256 = [sh0 | sh_1[1]].
    lstm_tile(s, widx, wtid,
              sh0_o, H_, sh_1 + B_*H_, H_, (const float*)nullptr, 0,
              W_ih1, H_, W_hh1, b_ih1, b_hh1, sc_1 + B_*H_,
              sh1_o, sc1_o, (w >> 3) * 16, (w & 7) * 16);
    grid_barrier();

    // ---- Phase 3: attention, 4 rows per block.
    {
        AttnBuf& a = s.at;
        const int warp = tid >> 5, lane = tid & 31;
        for (int r = 0; r < 4; r++) {
            const int b = bid * 4 + r;
            if (tid < 32) a.sq[tid] = __ldcg(((const float4*)(sh1_o + (size_t)b * H_)) + tid);
            __syncthreads();
            const float4 qv = a.sq[lane];

            // scores
            const float4* kbase = (const float4*)(hk + (size_t)b * (T_ * H_));
            {
                const int tbeg = warp * 128;
                #pragma unroll 8
                for (int t = tbeg; t < tbeg + 128; t++) {
                    float4 v = kbase[(size_t)t * 32 + lane];
                    float d = v.x*qv.x + v.y*qv.y + v.z*qv.z + v.w*qv.w;
                    d += __shfl_xor_sync(0xffffffffu, d, 16);
                    d += __shfl_xor_sync(0xffffffffu, d, 8);
                    d += __shfl_xor_sync(0xffffffffu, d, 4);
                    d += __shfl_xor_sync(0xffffffffu, d, 2);
                    d += __shfl_xor_sync(0xffffffffu, d, 1);
                    if (lane == 0) a.sa[t] = d;
                }
            }
            __syncthreads();

            // masked renormalized softmax
            {
                const float* mk = mask + (size_t)b * T_;
                float loc[4];
                float mx = -1e30f;
                #pragma unroll
                for (int i = 0; i < 4; i++) { loc[i] = a.sa[tid + i*512]; mx = fmaxf(mx, loc[i]); }
                a.red[tid] = mx; __syncthreads();
                for (int st = 256; st > 0; st >>= 1) {
                    if (tid < st) a.red[tid] = fmaxf(a.red[tid], a.red[tid + st]);
                    __syncthreads();
                }
                mx = a.red[0]; __syncthreads();
                float sum = 0.f;
                #pragma unroll
                for (int i = 0; i < 4; i++) {
                    float e = __expf(loc[i] - mx) * mk[tid + i*512];
                    loc[i] = e; sum += e;
                }
                a.red[tid] = sum; __syncthreads();
                for (int st = 256; st > 0; st >>= 1) {
                    if (tid < st) a.red[tid] += a.red[tid + st];
                    __syncthreads();
                }
                const float inv = 1.f / a.red[0];
                #pragma unroll
                for (int i = 0; i < 4; i++) {
                    float at = loc[i] * inv;
                    a.sa[tid + i*512] = at;
                    if (b == 0) att_o[tid + i*512] = at;
                }
            }
            __syncthreads();

            // context
            const float4* vbase = (const float4*)(hv + (size_t)b * (T_ * H_));
            float4 acc0 = make_float4(0.f,0.f,0.f,0.f);
            float4 acc1 = make_float4(0.f,0.f,0.f,0.f);
            #pragma unroll 4
            for (int t = warp; t < T_; t += 32) {
                float av = a.sa[t];
                float4 v = vbase[(size_t)t * 32 + lane];
                acc0.x = fmaf(av, v.x, acc0.x);
                acc0.y = fmaf(av, v.y, acc0.y);
                acc0.z = fmaf(av, v.z, acc0.z);
                acc0.w = fmaf(av, v.w, acc0.w);
                float av2 = a.sa[t + 16];
                float4 v2 = vbase[(size_t)(t + 16) * 32 + lane];
                acc1.x = fmaf(av2, v2.x, acc1.x);
                acc1.y = fmaf(av2, v2.y, acc1.y);
                acc1.z = fmaf(av2, v2.z, acc1.z);
                acc1.w = fmaf(av2, v2.w, acc1.w);
            }
            acc0.x += acc1.x; acc0.y += acc1.y; acc0.z += acc1.z; acc0.w += acc1.w;
            a.part[warp][lane] = acc0;
            __syncthreads();
            if (warp == 0) {
                float4 sm = a.part[0][lane];
                #pragma unroll
                for (int ww = 1; ww < 16; ww++) {
                    float4 p = a.part[ww][lane];
                    sm.x += p.x; sm.y += p.y; sm.z += p.z; sm.w += p.w;
                }
                ((float4*)(c_o + (size_t)b * H_))[lane] = sm;
            }
            __syncthreads();
        }
    }
    grid_barrier();

    // ---- Phase 4: head GEMM. 64 tiles (32 row x 2 col); workers duplicate.
    {
        const int t = w & 63;
        head_tile(s, widx, wtid, sh1_o, c_o, W1, W2, b1, b2,
                  (t >> 1) * 16, (t & 1) * 64);
    }
    grid_barrier();

    // ---- Phase 5: BN stats, block = feature (NBLK == H_).
    {
        BnBuf& bb = s.bn;
        const int f = bid;
        float v = __ldcg(&g_pre[(size_t)tid * H_ + f]);
        bb.rs[tid] = v; bb.rq[tid] = v * v;
        __syncthreads();
        for (int st = 256; st > 0; st >>= 1) {
            if (tid < st) { bb.rs[tid] += bb.rs[tid + st]; bb.rq[tid] += bb.rq[tid + st]; }
            __syncthreads();
        }
        if (tid == 0) {
            float mn = bb.rs[0] * (1.f / 512.f);
            g_mean[f] = mn;
            g_var[f] = bb.rq[0] * (1.f / 512.f) - mn * mn;
        }
    }
    grid_barrier();

    // ---- Phase 6: BN apply + ReLU + final GEMV, 4 rows per block.
    {
        FinBuf& fb = s.fin;
        const int grp = tid >> 7, f = tid & 127;
        const int b = bid * 4 + grp;
        float v = __ldcg(&g_pre[(size_t)b * H_ + f]);
        float n = (v - __ldcg(&g_mean[f])) * rsqrtf(__ldcg(&g_var[f]) + 1e-5f) * gamma[f] + beta[f];
        fb.sn[grp][f] = fmaxf(n, 0.f);
        __syncthreads();
        const int lw = (tid & 127) >> 5, lane = tid & 31;
        float x0 = fb.sn[grp][lane],      x1 = fb.sn[grp][lane + 32];
        float x2 = fb.sn[grp][lane + 64], x3 = fb.sn[grp][lane + 96];
        for (int vo = lw; vo < V_; vo += 4) {
            const float* wv = W3 + (size_t)vo * H_;
            float d = x0*wv[lane] + x1*wv[lane+32] + x2*wv[lane+64] + x3*wv[lane+96];
            d += __shfl_xor_sync(0xffffffffu, d, 16);
            d += __shfl_xor_sync(0xffffffffu, d, 8);
            d += __shfl_xor_sync(0xffffffffu, d, 4);
            d += __shfl_xor_sync(0xffffffffu, d, 2);
            d += __shfl_xor_sync(0xffffffffu, d, 1);
            if (lane == 0) d_out[(size_t)b * V_ + vo] = d + b3[vo];
        }
    }
}

// ---------------------------------------------------------------------------
extern "C" void kernel_launch(void* const* d_in, const int* in_sizes, int n_in,
                              void* d_out_v, int out_size) {
    const float* hk    = (const float*)d_in[0];
    const float* hv    = (const float*)d_in[1];
    const float* y_1   = (const float*)d_in[2];
    const float* c_1   = (const float*)d_in[3];
    const float* sh_1  = (const float*)d_in[4];
    const float* sc_1  = (const float*)d_in[5];
    const float* mask  = (const float*)d_in[6];
    const float* W_ih0 = (const float*)d_in[7];
    const float* W_hh0 = (const float*)d_in[8];
    const float* b_ih0 = (const float*)d_in[9];
    const float* b_hh0 = (const float*)d_in[10];
    const float* W_ih1 = (const float*)d_in[11];
    const float* W_hh1 = (const float*)d_in[12];
    const float* b_ih1 = (const float*)d_in[13];
    const float* b_hh1 = (const float*)d_in[14];
    const float* W1    = (const float*)d_in[15];
    const float* b1    = (const float*)d_in[16];
    const float* W2    = (const float*)d_in[17];
    const float* b2    = (const float*)d_in[18];
    const float* W3    = (const float*)d_in[19];
    const float* b3    = (const float*)d_in[20];
    const float* gamma = (const float*)d_in[21];
    const float* beta  = (const float*)d_in[22];
    float* d_out = (float*)d_out_v;
    (void)in_sizes; (void)n_in; (void)out_size;

    k_mega<<<NBLK, NTHR>>>(hk, hv, y_1, c_1, sh_1, sc_1, mask,
                           W_ih0, W_hh0, b_ih0, b_hh0,
                           W_ih1, W_hh1, b_ih1, b_hh1,
                           W1, b1, W2, b2, W3, b3, gamma, beta, d_out);
}

// round 8
// speedup vs baseline: 1.0441x; 1.0441x over previous
#include <cuda_runtime.h>
#include <math.h>

// Problem constants
#define B_ 512
#define T_ 2048
#define H_ 128
#define E_ 256
#define V_ 34

// Output layout: (out[B,V], c[B,H], sh0[B,H], sh1[B,H], sc0[B,H], sc1[B,H], atten_vec[T])
#define OFF_OUT 0
#define OFF_C   (B_*V_)
#define OFF_SH0 (OFF_C   + B_*H_)
#define OFF_SH1 (OFF_SH0 + B_*H_)
#define OFF_SC0 (OFF_SH1 + B_*H_)
#define OFF_SC1 (OFF_SC0 + B_*H_)
#define OFF_ATT (OFF_SC1 + B_*H_)

// Scratch (__device__ globals; no allocations allowed)
__device__ float g_pre[B_*H_];   // head pre-BN output
__device__ float g_mean[H_];
__device__ float g_var[H_];

__device__ __forceinline__ float sigm(float x) { return 1.f / (1.f + __expf(-x)); }

struct GemmBuf { float Xs[2][16][17]; float Ws[2][16][68]; };

// ---------------------------------------------------------------------------
// One split-K GEMM worker: 256 threads compute a 16(batch) x 64(col) tile
// over k in [kofs, kofs + nt*16). X is the virtual concat [A|Bp|Cp] (row-major
// segment widths ka/kb/kc); W is the virtual concat [Wih|Whh] by column k,
// with per-thread precomputed output-row indices wn[4] for its 4 loader cols.
// Double-buffered; both workers in a block call with the SAME nt so the
// block-wide __syncthreads sequence matches.
// ---------------------------------------------------------------------------
__device__ __forceinline__ void gemm_worker(
    GemmBuf& g, int wtid,
    const float* __restrict__ A, int ka,
    const float* __restrict__ Bp, int kb,
    const float* __restrict__ Cp, int kc,
    const float* __restrict__ Wih, int Kin,
    const float* __restrict__ Whh,
    int m0, const int* wn, int kofs, int nt, float acc[4])
{
    const int tx = wtid & 15, ty = wtid >> 4;
    const int lkk = tx, lr = ty;

    // prologue: tile 0
    {
        int k = kofs + lkk;
        float x0;
        if (k < ka)           x0 = A[(m0+lr)*ka + k];
        else if (k < ka + kb) x0 = Bp[(m0+lr)*kb + k - ka];
        else                  x0 = Cp[(m0+lr)*kc + k - ka - kb];
        g.Xs[0][lkk][lr] = x0;
        #pragma unroll
        for (int p = 0; p < 4; p++)
            g.Ws[0][lkk][lr + p*16] = (k < Kin) ? Wih[wn[p]*Kin + k] : Whh[wn[p]*H_ + k - Kin];
    }
    __syncthreads();

    for (int it = 0; it < nt; it++) {
        const int cur = it & 1, nxt = cur ^ 1;
        float px0 = 0.f, pw[4] = {0.f,0.f,0.f,0.f};
        const bool more = (it + 1 < nt);
        if (more) {
            int k = kofs + (it + 1) * 16 + lkk;
            if (k < ka)           px0 = A[(m0+lr)*ka + k];
            else if (k < ka + kb) px0 = Bp[(m0+lr)*kb + k - ka];
            else                  px0 = Cp[(m0+lr)*kc + k - ka - kb];
            #pragma unroll
            for (int p = 0; p < 4; p++)
                pw[p] = (k < Kin) ? Wih[wn[p]*Kin + k] : Whh[wn[p]*H_ + k - Kin];
        }
        #pragma unroll
        for (int kk = 0; kk < 16; kk++) {
            float x0 = g.Xs[cur][kk][ty];
            float4 wv = *(const float4*)&g.Ws[cur][kk][tx*4];
            acc[0] = fmaf(x0, wv.x, acc[0]);
            acc[1] = fmaf(x0, wv.y, acc[1]);
            acc[2] = fmaf(x0, wv.z, acc[2]);
            acc[3] = fmaf(x0, wv.w, acc[3]);
        }
        if (more) {
            g.Xs[nxt][lkk][lr] = px0;
            #pragma unroll
            for (int p = 0; p < 4; p++) g.Ws[nxt][lkk][lr + p*16] = pw[p];
            __syncthreads();
        }
    }
}

// ---------------------------------------------------------------------------
// Fused LSTM cell, in-block split-K (2 workers x 256 thr).
// Tile 16 rows x 16 h (64 gate cols, col = h_local*4 + gate).
// Grid (H/16=8, B/16=32) = 256 blocks x 512 threads.
// ---------------------------------------------------------------------------
__global__ void __launch_bounds__(512) k_lstm(
    const float* __restrict__ A, int ka,
    const float* __restrict__ Bp, int kb,
    const float* __restrict__ Cp, int kc,
    const float* __restrict__ Wih, int Kin,
    const float* __restrict__ Whh,
    const float* __restrict__ bih, const float* __restrict__ bhh,
    const float* __restrict__ c_prev,
    float* __restrict__ h_out, float* __restrict__ c_out)
{
    __shared__ GemmBuf g[2];
    __shared__ float comb[256][4];
    const int tid = threadIdx.x;
    const int widx = tid >> 8;          // worker 0/1
    const int wtid = tid & 255;
    const int tx = wtid & 15, ty = wtid >> 4;
    const int m0 = blockIdx.y * 16;
    const int h0 = blockIdx.x * 16;
    const int lr = ty;

    int wn[4];
    #pragma unroll
    for (int p = 0; p < 4; p++) {
        int c = lr + p * 16;
        wn[p] = (c & 3) * H_ + h0 + (c >> 2);   // gate*H + h
    }

    const int K = ka + kb + kc;
    const int halfK = K >> 1;
    const int nt = halfK >> 4;

    float acc[4] = {};
    gemm_worker(g[widx], wtid, A, ka, Bp, kb, Cp, kc, Wih, Kin, Whh,
                m0, wn, widx * halfK, nt, acc);

    if (widx == 1) {
        #pragma unroll
        for (int j = 0; j < 4; j++) comb[wtid][j] = acc[j];
    }
    __syncthreads();
    if (widx == 0) {
        #pragma unroll
        for (int j = 0; j < 4; j++) acc[j] += comb[wtid][j];
        const int h = h0 + tx, m = m0 + ty;
        float ig = sigm(acc[0] + bih[h]         + bhh[h]);
        float fg = sigm(acc[1] + bih[H_ + h]    + bhh[H_ + h]);
        float gg = tanhf(acc[2] + bih[2*H_ + h] + bhh[2*H_ + h]);
        float og = sigm(acc[3] + bih[3*H_ + h]  + bhh[3*H_ + h]);
        float cn = fg * c_prev[m*H_ + h] + ig * gg;
        c_out[m*H_ + h] = cn;
        h_out[m*H_ + h] = og * tanhf(cn);
    }
}

// ---------------------------------------------------------------------------
// Fused head GEMM, in-block split-K: pre = [sh1|c] @ [W1|W2]^T + b1 + b2.
// Tile 16x64, grid (2, 32) = 64 blocks x 512 threads; each worker K=128.
// ---------------------------------------------------------------------------
__global__ void __launch_bounds__(512) k_head(
    const float* __restrict__ sh1, const float* __restrict__ cvec,
    const float* __restrict__ W1, const float* __restrict__ W2,
    const float* __restrict__ b1, const float* __restrict__ b2)
{
    __shared__ GemmBuf g[2];
    __shared__ float comb[256][4];
    const int tid = threadIdx.x;
    const int widx = tid >> 8;
    const int wtid = tid & 255;
    const int tx = wtid & 15, ty = wtid >> 4;
    const int m0 = blockIdx.y * 16;
    const int n0 = blockIdx.x * 64;
    const int lr = ty;

    int wn[4];
    #pragma unroll
    for (int p = 0; p < 4; p++) wn[p] = n0 + lr + p * 16;

    const int nt = 8;  // K=256, half = 128

    float acc[4] = {};
    gemm_worker(g[widx], wtid, sh1, H_, cvec, H_, (const float*)nullptr, 0,
                W1, H_, W2, m0, wn, widx * 128, nt, acc);

    if (widx == 1) {
        #pragma unroll
        for (int j = 0; j < 4; j++) comb[wtid][j] = acc[j];
    }
    __syncthreads();
    if (widx == 0) {
        const int n = n0 + tx*4;
        const int m = m0 + ty;
        #pragma unroll
        for (int j = 0; j < 4; j++)
            g_pre[(size_t)m*H_ + n + j] = acc[j] + comb[wtid][j] + b1[n+j] + b2[n+j];
    }
}

// ---------------------------------------------------------------------------
// Fused attention: scores + masked renormalized softmax + context, one block
// per batch row. 512 threads (16 warps). hk/hv each streamed exactly once.
// ---------------------------------------------------------------------------
__global__ void __launch_bounds__(512) k_attn(
    const float* __restrict__ hk, const float* __restrict__ hv,
    const float* __restrict__ q, const float* __restrict__ mask,
    float* __restrict__ c_out, float* __restrict__ att0)
{
    __shared__ float  sa[T_];          // scores -> attn (in place)
    __shared__ float4 sq[32];
    __shared__ float4 part[16][32];
    __shared__ float  red[512];
    const int b = blockIdx.x, tid = threadIdx.x;
    const int warp = tid >> 5, lane = tid & 31;

    if (tid < 32) sq[tid] = ((const float4*)(q + (size_t)b * H_))[tid];
    __syncthreads();
    const float4 qv = sq[lane];

    // Phase 1: scores. Warp w handles t in [w*128, (w+1)*128).
    const float4* kbase = (const float4*)(hk + (size_t)b * (T_ * H_));
    {
        const int tbeg = warp * 128;
        #pragma unroll 8
        for (int t = tbeg; t < tbeg + 128; t++) {
            float4 v = kbase[(size_t)t * 32 + lane];
            float d = v.x*qv.x + v.y*qv.y + v.z*qv.z + v.w*qv.w;
            d += __shfl_xor_sync(0xffffffffu, d, 16);
            d += __shfl_xor_sync(0xffffffffu, d, 8);
            d += __shfl_xor_sync(0xffffffffu, d, 4);
            d += __shfl_xor_sync(0xffffffffu, d, 2);
            d += __shfl_xor_sync(0xffffffffu, d, 1);
            if (lane == 0) sa[t] = d;
        }
    }
    __syncthreads();

    // Phase 2: masked, renormalized softmax (4 elems/thread)
    {
        const float* mk = mask + (size_t)b * T_;
        float loc[4];
        float mx = -1e30f;
        #pragma unroll
        for (int i = 0; i < 4; i++) { loc[i] = sa[tid + i*512]; mx = fmaxf(mx, loc[i]); }
        red[tid] = mx; __syncthreads();
        for (int st = 256; st > 0; st >>= 1) {
            if (tid < st) red[tid] = fmaxf(red[tid], red[tid + st]);
            __syncthreads();
        }
        mx = red[0]; __syncthreads();
        float sum = 0.f;
        #pragma unroll
        for (int i = 0; i < 4; i++) {
            float e = __expf(loc[i] - mx) * mk[tid + i*512];
            loc[i] = e; sum += e;
        }
        red[tid] = sum; __syncthreads();
        for (int st = 256; st > 0; st >>= 1) {
            if (tid < st) red[tid] += red[tid + st];
            __syncthreads();
        }
        const float inv = 1.f / red[0];
        #pragma unroll
        for (int i = 0; i < 4; i++) {
            float a = loc[i] * inv;
            sa[tid + i*512] = a;
            if (b == 0) att0[tid + i*512] = a;
        }
    }
    __syncthreads();

    // Phase 3: context. 16 warps split T, lane owns 4 h (float4), 2 accums.
    const float4* vbase = (const float4*)(hv + (size_t)b * (T_ * H_));
    float4 acc0 = make_float4(0.f, 0.f, 0.f, 0.f);
    float4 acc1 = make_float4(0.f, 0.f, 0.f, 0.f);
    #pragma unroll 4
    for (int t = warp; t < T_; t += 32) {
        float a = sa[t];
        float4 v = vbase[(size_t)t * 32 + lane];
        acc0.x = fmaf(a, v.x, acc0.x);
        acc0.y = fmaf(a, v.y, acc0.y);
        acc0.z = fmaf(a, v.z, acc0.z);
        acc0.w = fmaf(a, v.w, acc0.w);
        float a2 = sa[t + 16];
        float4 v2 = vbase[(size_t)(t + 16) * 32 + lane];
        acc1.x = fmaf(a2, v2.x, acc1.x);
        acc1.y = fmaf(a2, v2.y, acc1.y);
        acc1.z = fmaf(a2, v2.z, acc1.z);
        acc1.w = fmaf(a2, v2.w, acc1.w);
    }
    acc0.x += acc1.x; acc0.y += acc1.y; acc0.z += acc1.z; acc0.w += acc1.w;
    part[warp][lane] = acc0;
    __syncthreads();
    if (warp == 0) {
        float4 s = part[0][lane];
        #pragma unroll
        for (int w = 1; w < 16; w++) {
            float4 p = part[w][lane];
            s.x += p.x; s.y += p.y; s.z += p.z; s.w += p.w;
        }
        ((float4*)(c_out + (size_t)b * H_))[lane] = s;
    }
}

// ---------------------------------------------------------------------------
// BatchNorm training stats over batch (block per feature).
// ---------------------------------------------------------------------------
__global__ void k_bn(void) {
    int f = blockIdx.x, tid = threadIdx.x;
    float v0 = g_pre[(size_t)tid * H_ + f];
    float v1 = g_pre[(size_t)(tid + 256) * H_ + f];
    __shared__ float rs[256], rq[256];
    rs[tid] = v0 + v1;
    rq[tid] = v0 * v0 + v1 * v1;
    __syncthreads();
    for (int st = 128; st > 0; st >>= 1) {
        if (tid < st) { rs[tid] += rs[tid + st]; rq[tid] += rq[tid + st]; }
        __syncthreads();
    }
    if (tid == 0) {
        float mn = rs[0] * (1.f / 512.f);
        g_mean[f] = mn;
        g_var[f] = rq[0] * (1.f / 512.f) - mn * mn;
    }
}

// ---------------------------------------------------------------------------
// BN apply + ReLU + final linear (block per b, 4 warps, warp-per-output GEMV).
// ---------------------------------------------------------------------------
__global__ void k_final(const float* __restrict__ gamma, const float* __restrict__ beta,
                        const float* __restrict__ W3, const float* __restrict__ b3,
                        float* __restrict__ out) {
    int b = blockIdx.x, f = threadIdx.x;
    const int warp = f >> 5, lane = f & 31;
    __shared__ float sn[H_];
    float v = g_pre[(size_t)b * H_ + f];
    float n = (v - g_mean[f]) * rsqrtf(g_var[f] + 1e-5f) * gamma[f] + beta[f];
    sn[f] = fmaxf(n, 0.f);
    __syncthreads();
    float x0 = sn[lane], x1 = sn[lane + 32], x2 = sn[lane + 64], x3 = sn[lane + 96];
    for (int vo = warp; vo < V_; vo += 4) {
        const float* w = W3 + (size_t)vo * H_;
        float d = x0 * w[lane] + x1 * w[lane + 32] + x2 * w[lane + 64] + x3 * w[lane + 96];
        d += __shfl_xor_sync(0xffffffffu, d, 16);
        d += __shfl_xor_sync(0xffffffffu, d, 8);
        d += __shfl_xor_sync(0xffffffffu, d, 4);
        d += __shfl_xor_sync(0xffffffffu, d, 2);
        d += __shfl_xor_sync(0xffffffffu, d, 1);
        if (lane == 0) out[(size_t)b * V_ + vo] = d + b3[vo];
    }
}

// ---------------------------------------------------------------------------
extern "C" void kernel_launch(void* const* d_in, const int* in_sizes, int n_in,
                              void* d_out_v, int out_size) {
    const float* hk    = (const float*)d_in[0];
    const float* hv    = (const float*)d_in[1];
    const float* y_1   = (const float*)d_in[2];
    const float* c_1   = (const float*)d_in[3];
    const float* sh_1  = (const float*)d_in[4];   // [2,B,H]
    const float* sc_1  = (const float*)d_in[5];   // [2,B,H]
    const float* mask  = (const float*)d_in[6];
    const float* W_ih0 = (const float*)d_in[7];   // [512, 384]
    const float* W_hh0 = (const float*)d_in[8];   // [512, 128]
    const float* b_ih0 = (const float*)d_in[9];
    const float* b_hh0 = (const float*)d_in[10];
    const float* W_ih1 = (const float*)d_in[11];  // [512, 128]
    const float* W_hh1 = (const float*)d_in[12];  // [512, 128]
    const float* b_ih1 = (const float*)d_in[13];
    const float* b_hh1 = (const float*)d_in[14];
    const float* W1    = (const float*)d_in[15];  // [128, 128]
    const float* b1    = (const float*)d_in[16];
    const float* W2    = (const float*)d_in[17];  // [128, 128]
    const float* b2    = (const float*)d_in[18];
    const float* W3    = (const float*)d_in[19];  // [34, 128]
    const float* b3    = (const float*)d_in[20];
    const float* gamma = (const float*)d_in[21];
    const float* beta  = (const float*)d_in[22];
    float* d_out = (float*)d_out_v;
    (void)in_sizes; (void)n_in; (void)out_size;

    // LSTM cell 0: X = [y_1(256) | c_1(128) | sh_1[0](128)], Kin=384, K=512
    k_lstm<<<dim3(H_/16, B_/16), 512>>>(
        y_1, E_, c_1, H_, sh_1, H_,
        W_ih0, E_ + H_, W_hh0, b_ih0, b_hh0,
        sc_1, d_out + OFF_SH0, d_out + OFF_SC0);

    // LSTM cell 1: X = [sh0(128) | sh_1[1](128)], Kin=128, K=256
    k_lstm<<<dim3(H_/16, B_/16), 512>>>(
        d_out + OFF_SH0, H_, sh_1 + B_*H_, H_, (const float*)nullptr, 0,
        W_ih1, H_, W_hh1, b_ih1, b_hh1,
        sc_1 + B_*H_, d_out + OFF_SH1, d_out + OFF_SC1);

    // Attention (fused scores + softmax + context)
    k_attn<<<B_, 512>>>(hk, hv, d_out + OFF_SH1, mask,
                        d_out + OFF_C, d_out + OFF_ATT);

    // Head
    k_head<<<dim3(2, B_/16), 512>>>(d_out + OFF_SH1, d_out + OFF_C, W1, W2, b1, b2);
    k_bn<<<H_, 256>>>();
    k_final<<<B_, 128>>>(gamma, beta, W3, b3, d_out + OFF_OUT);
}

// round 9
// speedup vs baseline: 1.1080x; 1.0612x over previous
#include <cuda_runtime.h>
#include <math.h>

// Problem constants
#define B_ 512
#define T_ 2048
#define H_ 128
#define E_ 256
#define V_ 34

// Output layout: (out[B,V], c[B,H], sh0[B,H], sh1[B,H], sc0[B,H], sc1[B,H], atten_vec[T])
#define OFF_OUT 0
#define OFF_C   (B_*V_)
#define OFF_SH0 (OFF_C   + B_*H_)
#define OFF_SH1 (OFF_SH0 + B_*H_)
#define OFF_SC0 (OFF_SH1 + B_*H_)
#define OFF_SC1 (OFF_SC0 + B_*H_)
#define OFF_ATT (OFF_SC1 + B_*H_)

// Scratch (__device__ globals; no allocations allowed)
__device__ float g_pre[B_*H_];   // head pre-BN output
__device__ float g_mean[H_];
__device__ float g_var[H_];

__device__ __forceinline__ float sigm(float x) { return 1.f / (1.f + __expf(-x)); }

// ---------------------------------------------------------------------------
// LSTM cell with in-block split-K on the proven 32-row tile.
// Tile: 32 batch rows x 16 h (64 gate cols, col = h_local*4 + gate).
// Block: 512 threads = 2 workers x 256; worker widx covers k in
// [widx*K/2, (widx+1)*K/2). Grid (H/16=8, B/32=16) = 128 blocks.
// X is the virtual concat [A|Bp|Cp]; W is [Wih|Whh] by k.
// ---------------------------------------------------------------------------
struct GemmBuf32 { float Xs[2][16][34]; float Ws[2][16][68]; };

__global__ void __launch_bounds__(512) k_lstm(
    const float* __restrict__ A, int ka,
    const float* __restrict__ Bp, int kb,
    const float* __restrict__ Cp, int kc,
    const float* __restrict__ Wih, int Kin,
    const float* __restrict__ Whh,
    const float* __restrict__ bih, const float* __restrict__ bhh,
    const float* __restrict__ c_prev,
    float* __restrict__ h_out, float* __restrict__ c_out)
{
    __shared__ GemmBuf32 gbuf[2];
    __shared__ float comb[256][8];
    const int tid = threadIdx.x;
    const int widx = tid >> 8;          // worker 0/1
    const int wtid = tid & 255;
    GemmBuf32& g = gbuf[widx];
    const int tx = wtid & 15, ty = wtid >> 4;
    const int m0 = blockIdx.y * 32;
    const int h0 = blockIdx.x * 16;
    const int lkk = wtid & 15, lr = wtid >> 4;

    const int K = ka + kb + kc;
    const int halfK = K >> 1;
    const int nt = halfK >> 4;
    const int kofs = widx * halfK;

    // W row index for each of this thread's 4 loader columns (col = lr + p*16)
    int wn[4];
    #pragma unroll
    for (int p = 0; p < 4; p++) {
        int c = lr + p * 16;
        wn[p] = (c & 3) * H_ + h0 + (c >> 2);   // gate*H + h
    }

    // prologue: tile 0 -> buf 0
    {
        int k = kofs + lkk;
        float x0, x1;
        if (k < ka)           { x0 = A[(m0+lr)*ka + k];            x1 = A[(m0+lr+16)*ka + k]; }
        else if (k < ka + kb) { x0 = Bp[(m0+lr)*kb + k - ka];      x1 = Bp[(m0+lr+16)*kb + k - ka]; }
        else                  { x0 = Cp[(m0+lr)*kc + k - ka - kb]; x1 = Cp[(m0+lr+16)*kc + k - ka - kb]; }
        g.Xs[0][lkk][lr] = x0; g.Xs[0][lkk][lr+16] = x1;
        #pragma unroll
        for (int p = 0; p < 4; p++)
            g.Ws[0][lkk][lr + p*16] = (k < Kin) ? Wih[wn[p]*Kin + k] : Whh[wn[p]*H_ + k - Kin];
    }
    __syncthreads();

    float acc[2][4] = {};
    for (int it = 0; it < nt; it++) {
        const int cur = it & 1, nxt = cur ^ 1;
        float px0 = 0.f, px1 = 0.f, pw[4] = {0.f,0.f,0.f,0.f};
        const bool more = (it + 1 < nt);
        if (more) {
            int k = kofs + (it + 1) * 16 + lkk;
            if (k < ka)           { px0 = A[(m0+lr)*ka + k];            px1 = A[(m0+lr+16)*ka + k]; }
            else if (k < ka + kb) { px0 = Bp[(m0+lr)*kb + k - ka];      px1 = Bp[(m0+lr+16)*kb + k - ka]; }
            else                  { px0 = Cp[(m0+lr)*kc + k - ka - kb]; px1 = Cp[(m0+lr+16)*kc + k - ka - kb]; }
            #pragma unroll
            for (int p = 0; p < 4; p++)
                pw[p] = (k < Kin) ? Wih[wn[p]*Kin + k] : Whh[wn[p]*H_ + k - Kin];
        }
        #pragma unroll
        for (int kk = 0; kk < 16; kk++) {
            float x0 = g.Xs[cur][kk][ty*2];
            float x1 = g.Xs[cur][kk][ty*2 + 1];
            float4 wv = *(const float4*)&g.Ws[cur][kk][tx*4];
            acc[0][0] = fmaf(x0, wv.x, acc[0][0]);
            acc[0][1] = fmaf(x0, wv.y, acc[0][1]);
            acc[0][2] = fmaf(x0, wv.z, acc[0][2]);
            acc[0][3] = fmaf(x0, wv.w, acc[0][3]);
            acc[1][0] = fmaf(x1, wv.x, acc[1][0]);
            acc[1][1] = fmaf(x1, wv.y, acc[1][1]);
            acc[1][2] = fmaf(x1, wv.z, acc[1][2]);
            acc[1][3] = fmaf(x1, wv.w, acc[1][3]);
        }
        if (more) {
            g.Xs[nxt][lkk][lr] = px0;
            g.Xs[nxt][lkk][lr+16] = px1;
            #pragma unroll
            for (int p = 0; p < 4; p++) g.Ws[nxt][lkk][lr + p*16] = pw[p];
            __syncthreads();
        }
    }

    // combine the two K-halves through smem, then epilogue on worker 0
    if (widx == 1) {
        #pragma unroll
        for (int r = 0; r < 2; r++)
            #pragma unroll
            for (int j = 0; j < 4; j++) comb[wtid][r*4 + j] = acc[r][j];
    }
    __syncthreads();
    if (widx == 0) {
        const int h = h0 + tx;
        const float bi = bih[h]         + bhh[h];
        const float bf = bih[H_ + h]    + bhh[H_ + h];
        const float bg = bih[2*H_ + h]  + bhh[2*H_ + h];
        const float bo = bih[3*H_ + h]  + bhh[3*H_ + h];
        #pragma unroll
        for (int r = 0; r < 2; r++) {
            const int m = m0 + ty*2 + r;
            float a0 = acc[r][0] + comb[wtid][r*4 + 0];
            float a1 = acc[r][1] + comb[wtid][r*4 + 1];
            float a2 = acc[r][2] + comb[wtid][r*4 + 2];
            float a3 = acc[r][3] + comb[wtid][r*4 + 3];
            float ig = sigm(a0 + bi);
            float fg = sigm(a1 + bf);
            float gg = tanhf(a2 + bg);
            float og = sigm(a3 + bo);
            float cn = fg * c_prev[m*H_ + h] + ig * gg;
            c_out[m*H_ + h] = cn;
            h_out[m*H_ + h] = og * tanhf(cn);
        }
    }
}

// ---------------------------------------------------------------------------
// Head GEMM, in-block split-K (R7 version, measured 11.6us):
// pre = [sh1|c] @ [W1|W2]^T + b1 + b2. Tile 16x64, grid (2,32) x 512 thr.
// ---------------------------------------------------------------------------
struct GemmBuf16 { float Xs[2][16][17]; float Ws[2][16][68]; };

__global__ void __launch_bounds__(512) k_head(
    const float* __restrict__ sh1, const float* __restrict__ cvec,
    const float* __restrict__ W1, const float* __restrict__ W2,
    const float* __restrict__ b1, const float* __restrict__ b2)
{
    __shared__ GemmBuf16 gbuf[2];
    __shared__ float comb[256][4];
    const int tid = threadIdx.x;
    const int widx = tid >> 8;
    const int wtid = tid & 255;
    GemmBuf16& g = gbuf[widx];
    const int tx = wtid & 15, ty = wtid >> 4;
    const int m0 = blockIdx.y * 16;
    const int n0 = blockIdx.x * 64;
    const int lkk = tx, lr = ty;
    const int nt = 8;                       // K=256, half=128
    const int kofs = widx * 128;

    // which source half this worker reads (worker0: sh1/W1, worker1: c/W2)
    const float* Xsrc = widx ? cvec : sh1;
    const float* Wsrc = widx ? W2 : W1;

    {
        int k = (kofs + lkk) & 127;
        g.Xs[0][lkk][lr] = Xsrc[(m0+lr)*H_ + k];
        #pragma unroll
        for (int p = 0; p < 4; p++)
            g.Ws[0][lkk][lr + p*16] = Wsrc[(n0 + lr + p*16)*H_ + k];
    }
    __syncthreads();

    float acc[4] = {};
    for (int it = 0; it < nt; it++) {
        const int cur = it & 1, nxt = cur ^ 1;
        float px0 = 0.f, pw[4] = {0.f,0.f,0.f,0.f};
        const bool more = (it + 1 < nt);
        if (more) {
            int k = ((it + 1) * 16 + lkk) & 127;
            px0 = Xsrc[(m0+lr)*H_ + k];
            #pragma unroll
            for (int p = 0; p < 4; p++) pw[p] = Wsrc[(n0+lr+p*16)*H_ + k];
        }
        #pragma unroll
        for (int kk = 0; kk < 16; kk++) {
            float x0 = g.Xs[cur][kk][ty];
            float4 wv = *(const float4*)&g.Ws[cur][kk][tx*4];
            acc[0] = fmaf(x0, wv.x, acc[0]);
            acc[1] = fmaf(x0, wv.y, acc[1]);
            acc[2] = fmaf(x0, wv.z, acc[2]);
            acc[3] = fmaf(x0, wv.w, acc[3]);
        }
        if (more) {
            g.Xs[nxt][lkk][lr] = px0;
            #pragma unroll
            for (int p = 0; p < 4; p++) g.Ws[nxt][lkk][lr + p*16] = pw[p];
            __syncthreads();
        }
    }

    if (widx == 1) {
        #pragma unroll
        for (int j = 0; j < 4; j++) comb[wtid][j] = acc[j];
    }
    __syncthreads();
    if (widx == 0) {
        const int n = n0 + tx*4;
        const int m = m0 + ty;
        #pragma unroll
        for (int j = 0; j < 4; j++)
            g_pre[(size_t)m*H_ + n + j] = acc[j] + comb[wtid][j] + b1[n+j] + b2[n+j];
    }
}

// ---------------------------------------------------------------------------
// Fused attention: scores + masked renormalized softmax + context, one block
// per batch row. 512 threads (16 warps). hk/hv each streamed exactly once.
// (Unchanged from the 233.5us kernel.)
// ---------------------------------------------------------------------------
__global__ void __launch_bounds__(512) k_attn(
    const float* __restrict__ hk, const float* __restrict__ hv,
    const float* __restrict__ q, const float* __restrict__ mask,
    float* __restrict__ c_out, float* __restrict__ att0)
{
    __shared__ float  sa[T_];
    __shared__ float4 sq[32];
    __shared__ float4 part[16][32];
    __shared__ float  red[512];
    const int b = blockIdx.x, tid = threadIdx.x;
    const int warp = tid >> 5, lane = tid & 31;

    if (tid < 32) sq[tid] = ((const float4*)(q + (size_t)b * H_))[tid];
    __syncthreads();
    const float4 qv = sq[lane];

    const float4* kbase = (const float4*)(hk + (size_t)b * (T_ * H_));
    {
        const int tbeg = warp * 128;
        #pragma unroll 8
        for (int t = tbeg; t < tbeg + 128; t++) {
            float4 v = kbase[(size_t)t * 32 + lane];
            float d = v.x*qv.x + v.y*qv.y + v.z*qv.z + v.w*qv.w;
            d += __shfl_xor_sync(0xffffffffu, d, 16);
            d += __shfl_xor_sync(0xffffffffu, d, 8);
            d += __shfl_xor_sync(0xffffffffu, d, 4);
            d += __shfl_xor_sync(0xffffffffu, d, 2);
            d += __shfl_xor_sync(0xffffffffu, d, 1);
            if (lane == 0) sa[t] = d;
        }
    }
    __syncthreads();

    {
        const float* mk = mask + (size_t)b * T_;
        float loc[4];
        float mx = -1e30f;
        #pragma unroll
        for (int i = 0; i < 4; i++) { loc[i] = sa[tid + i*512]; mx = fmaxf(mx, loc[i]); }
        red[tid] = mx; __syncthreads();
        for (int st = 256; st > 0; st >>= 1) {
            if (tid < st) red[tid] = fmaxf(red[tid], red[tid + st]);
            __syncthreads();
        }
        mx = red[0]; __syncthreads();
        float sum = 0.f;
        #pragma unroll
        for (int i = 0; i < 4; i++) {
            float e = __expf(loc[i] - mx) * mk[tid + i*512];
            loc[i] = e; sum += e;
        }
        red[tid] = sum; __syncthreads();
        for (int st = 256; st > 0; st >>= 1) {
            if (tid < st) red[tid] += red[tid + st];
            __syncthreads();
        }
        const float inv = 1.f / red[0];
        #pragma unroll
        for (int i = 0; i < 4; i++) {
            float a = loc[i] * inv;
            sa[tid + i*512] = a;
            if (b == 0) att0[tid + i*512] = a;
        }
    }
    __syncthreads();

    const float4* vbase = (const float4*)(hv + (size_t)b * (T_ * H_));
    float4 acc0 = make_float4(0.f, 0.f, 0.f, 0.f);
    float4 acc1 = make_float4(0.f, 0.f, 0.f, 0.f);
    #pragma unroll 4
    for (int t = warp; t < T_; t += 32) {
        float a = sa[t];
        float4 v = vbase[(size_t)t * 32 + lane];
        acc0.x = fmaf(a, v.x, acc0.x);
        acc0.y = fmaf(a, v.y, acc0.y);
        acc0.z = fmaf(a, v.z, acc0.z);
        acc0.w = fmaf(a, v.w, acc0.w);
        float a2 = sa[t + 16];
        float4 v2 = vbase[(size_t)(t + 16) * 32 + lane];
        acc1.x = fmaf(a2, v2.x, acc1.x);
        acc1.y = fmaf(a2, v2.y, acc1.y);
        acc1.z = fmaf(a2, v2.z, acc1.z);
        acc1.w = fmaf(a2, v2.w, acc1.w);
    }
    acc0.x += acc1.x; acc0.y += acc1.y; acc0.z += acc1.z; acc0.w += acc1.w;
    part[warp][lane] = acc0;
    __syncthreads();
    if (warp == 0) {
        float4 s = part[0][lane];
        #pragma unroll
        for (int w = 1; w < 16; w++) {
            float4 p = part[w][lane];
            s.x += p.x; s.y += p.y; s.z += p.z; s.w += p.w;
        }
        ((float4*)(c_out + (size_t)b * H_))[lane] = s;
    }
}

// ---------------------------------------------------------------------------
// BatchNorm training stats over batch (block per feature).
// ---------------------------------------------------------------------------
__global__ void k_bn(void) {
    int f = blockIdx.x, tid = threadIdx.x;
    float v0 = g_pre[(size_t)tid * H_ + f];
    float v1 = g_pre[(size_t)(tid + 256) * H_ + f];
    __shared__ float rs[256], rq[256];
    rs[tid] = v0 + v1;
    rq[tid] = v0 * v0 + v1 * v1;
    __syncthreads();
    for (int st = 128; st > 0; st >>= 1) {
        if (tid < st) { rs[tid] += rs[tid + st]; rq[tid] += rq[tid + st]; }
        __syncthreads();
    }
    if (tid == 0) {
        float mn = rs[0] * (1.f / 512.f);
        g_mean[f] = mn;
        g_var[f] = rq[0] * (1.f / 512.f) - mn * mn;
    }
}

// ---------------------------------------------------------------------------
// BN apply + ReLU + final linear (block per b, 4 warps, warp-per-output GEMV).
// ---------------------------------------------------------------------------
__global__ void k_final(const float* __restrict__ gamma, const float* __restrict__ beta,
                        const float* __restrict__ W3, const float* __restrict__ b3,
                        float* __restrict__ out) {
    int b = blockIdx.x, f = threadIdx.x;
    const int warp = f >> 5, lane = f & 31;
    __shared__ float sn[H_];
    float v = g_pre[(size_t)b * H_ + f];
    float n = (v - g_mean[f]) * rsqrtf(g_var[f] + 1e-5f) * gamma[f] + beta[f];
    sn[f] = fmaxf(n, 0.f);
    __syncthreads();
    float x0 = sn[lane], x1 = sn[lane + 32], x2 = sn[lane + 64], x3 = sn[lane + 96];
    for (int vo = warp; vo < V_; vo += 4) {
        const float* w = W3 + (size_t)vo * H_;
        float d = x0 * w[lane] + x1 * w[lane + 32] + x2 * w[lane + 64] + x3 * w[lane + 96];
        d += __shfl_xor_sync(0xffffffffu, d, 16);
        d += __shfl_xor_sync(0xffffffffu, d, 8);
        d += __shfl_xor_sync(0xffffffffu, d, 4);
        d += __shfl_xor_sync(0xffffffffu, d, 2);
        d += __shfl_xor_sync(0xffffffffu, d, 1);
        if (lane == 0) out[(size_t)b * V_ + vo] = d + b3[vo];
    }
}

// ---------------------------------------------------------------------------
extern "C" void kernel_launch(void* const* d_in, const int* in_sizes, int n_in,
                              void* d_out_v, int out_size) {
    const float* hk    = (const float*)d_in[0];
    const float* hv    = (const float*)d_in[1];
    const float* y_1   = (const float*)d_in[2];
    const float* c_1   = (const float*)d_in[3];
    const float* sh_1  = (const float*)d_in[4];   // [2,B,H]
    const float* sc_1  = (const float*)d_in[5];   // [2,B,H]
    const float* mask  = (const float*)d_in[6];
    const float* W_ih0 = (const float*)d_in[7];   // [512, 384]
    const float* W_hh0 = (const float*)d_in[8];   // [512, 128]
    const float* b_ih0 = (const float*)d_in[9];
    const float* b_hh0 = (const float*)d_in[10];
    const float* W_ih1 = (const float*)d_in[11];  // [512, 128]
    const float* W_hh1 = (const float*)d_in[12];  // [512, 128]
    const float* b_ih1 = (const float*)d_in[13];
    const float* b_hh1 = (const float*)d_in[14];
    const float* W1    = (const float*)d_in[15];  // [128, 128]
    const float* b1    = (const float*)d_in[16];
    const float* W2    = (const float*)d_in[17];  // [128, 128]
    const float* b2    = (const float*)d_in[18];
    const float* W3    = (const float*)d_in[19];  // [34, 128]
    const float* b3    = (const float*)d_in[20];
    const float* gamma = (const float*)d_in[21];
    const float* beta  = (const float*)d_in[22];
    float* d_out = (float*)d_out_v;
    (void)in_sizes; (void)n_in; (void)out_size;

    // LSTM cell 0: X = [y_1(256) | c_1(128) | sh_1[0](128)], Kin=384, K=512
    k_lstm<<<dim3(H_/16, B_/32), 512>>>(
        y_1, E_, c_1, H_, sh_1, H_,
        W_ih0, E_ + H_, W_hh0, b_ih0, b_hh0,
        sc_1, d_out + OFF_SH0, d_out + OFF_SC0);

    // LSTM cell 1: X = [sh0(128) | sh_1[1](128)], Kin=128, K=256
    k_lstm<<<dim3(H_/16, B_/32), 512>>>(
        d_out + OFF_SH0, H_, sh_1 + B_*H_, H_, (const float*)nullptr, 0,
        W_ih1, H_, W_hh1, b_ih1, b_hh1,
        sc_1 + B_*H_, d_out + OFF_SH1, d_out + OFF_SC1);

    // Attention (fused scores + softmax + context)
    k_attn<<<B_, 512>>>(hk, hv, d_out + OFF_SH1, mask,
                        d_out + OFF_C, d_out + OFF_ATT);

    // Head
    k_head<<<dim3(2, B_/16), 512>>>(d_out + OFF_SH1, d_out + OFF_C, W1, W2, b1, b2);
    k_bn<<<H_, 256>>>();
    k_final<<<B_, 128>>>(gamma, beta, W3, b3, d_out + OFF_OUT);
}

// round 10
// speedup vs baseline: 1.1691x; 1.0551x over previous
#include <cuda_runtime.h>
#include <math.h>

// Problem constants
#define B_ 512
#define T_ 2048
#define H_ 128
#define E_ 256
#define V_ 34

// Output layout: (out[B,V], c[B,H], sh0[B,H], sh1[B,H], sc0[B,H], sc1[B,H], atten_vec[T])
#define OFF_OUT 0
#define OFF_C   (B_*V_)
#define OFF_SH0 (OFF_C   + B_*H_)
#define OFF_SH1 (OFF_SH0 + B_*H_)
#define OFF_SC0 (OFF_SH1 + B_*H_)
#define OFF_SC1 (OFF_SC0 + B_*H_)
#define OFF_ATT (OFF_SC1 + B_*H_)

// Scratch (__device__ globals; no allocations allowed)
__device__ float g_pre[B_*H_];   // head pre-BN output
__device__ float g_mean[H_];
__device__ float g_var[H_];

__device__ __forceinline__ float sigm(float x) { return 1.f / (1.f + __expf(-x)); }

// ---------------------------------------------------------------------------
// LSTM cell with in-block split-K on the proven 32-row tile. (R9, unchanged)
// ---------------------------------------------------------------------------
struct GemmBuf32 { float Xs[2][16][34]; float Ws[2][16][68]; };

__global__ void __launch_bounds__(512) k_lstm(
    const float* __restrict__ A, int ka,
    const float* __restrict__ Bp, int kb,
    const float* __restrict__ Cp, int kc,
    const float* __restrict__ Wih, int Kin,
    const float* __restrict__ Whh,
    const float* __restrict__ bih, const float* __restrict__ bhh,
    const float* __restrict__ c_prev,
    float* __restrict__ h_out, float* __restrict__ c_out)
{
    __shared__ GemmBuf32 gbuf[2];
    __shared__ float comb[256][8];
    const int tid = threadIdx.x;
    const int widx = tid >> 8;          // worker 0/1
    const int wtid = tid & 255;
    GemmBuf32& g = gbuf[widx];
    const int tx = wtid & 15, ty = wtid >> 4;
    const int m0 = blockIdx.y * 32;
    const int h0 = blockIdx.x * 16;
    const int lkk = wtid & 15, lr = wtid >> 4;

    const int K = ka + kb + kc;
    const int halfK = K >> 1;
    const int nt = halfK >> 4;
    const int kofs = widx * halfK;

    int wn[4];
    #pragma unroll
    for (int p = 0; p < 4; p++) {
        int c = lr + p * 16;
        wn[p] = (c & 3) * H_ + h0 + (c >> 2);   // gate*H + h
    }

    {
        int k = kofs + lkk;
        float x0, x1;
        if (k < ka)           { x0 = A[(m0+lr)*ka + k];            x1 = A[(m0+lr+16)*ka + k]; }
        else if (k < ka + kb) { x0 = Bp[(m0+lr)*kb + k - ka];      x1 = Bp[(m0+lr+16)*kb + k - ka]; }
        else                  { x0 = Cp[(m0+lr)*kc + k - ka - kb]; x1 = Cp[(m0+lr+16)*kc + k - ka - kb]; }
        g.Xs[0][lkk][lr] = x0; g.Xs[0][lkk][lr+16] = x1;
        #pragma unroll
        for (int p = 0; p < 4; p++)
            g.Ws[0][lkk][lr + p*16] = (k < Kin) ? Wih[wn[p]*Kin + k] : Whh[wn[p]*H_ + k - Kin];
    }
    __syncthreads();

    float acc[2][4] = {};
    for (int it = 0; it < nt; it++) {
        const int cur = it & 1, nxt = cur ^ 1;
        float px0 = 0.f, px1 = 0.f, pw[4] = {0.f,0.f,0.f,0.f};
        const bool more = (it + 1 < nt);
        if (more) {
            int k = kofs + (it + 1) * 16 + lkk;
            if (k < ka)           { px0 = A[(m0+lr)*ka + k];            px1 = A[(m0+lr+16)*ka + k]; }
            else if (k < ka + kb) { px0 = Bp[(m0+lr)*kb + k - ka];      px1 = Bp[(m0+lr+16)*kb + k - ka]; }
            else                  { px0 = Cp[(m0+lr)*kc + k - ka - kb]; px1 = Cp[(m0+lr+16)*kc + k - ka - kb]; }
            #pragma unroll
            for (int p = 0; p < 4; p++)
                pw[p] = (k < Kin) ? Wih[wn[p]*Kin + k] : Whh[wn[p]*H_ + k - Kin];
        }
        #pragma unroll
        for (int kk = 0; kk < 16; kk++) {
            float x0 = g.Xs[cur][kk][ty*2];
            float x1 = g.Xs[cur][kk][ty*2 + 1];
            float4 wv = *(const float4*)&g.Ws[cur][kk][tx*4];
            acc[0][0] = fmaf(x0, wv.x, acc[0][0]);
            acc[0][1] = fmaf(x0, wv.y, acc[0][1]);
            acc[0][2] = fmaf(x0, wv.z, acc[0][2]);
            acc[0][3] = fmaf(x0, wv.w, acc[0][3]);
            acc[1][0] = fmaf(x1, wv.x, acc[1][0]);
            acc[1][1] = fmaf(x1, wv.y, acc[1][1]);
            acc[1][2] = fmaf(x1, wv.z, acc[1][2]);
            acc[1][3] = fmaf(x1, wv.w, acc[1][3]);
        }
        if (more) {
            g.Xs[nxt][lkk][lr] = px0;
            g.Xs[nxt][lkk][lr+16] = px1;
            #pragma unroll
            for (int p = 0; p < 4; p++) g.Ws[nxt][lkk][lr + p*16] = pw[p];
            __syncthreads();
        }
    }

    if (widx == 1) {
        #pragma unroll
        for (int r = 0; r < 2; r++)
            #pragma unroll
            for (int j = 0; j < 4; j++) comb[wtid][r*4 + j] = acc[r][j];
    }
    __syncthreads();
    if (widx == 0) {
        const int h = h0 + tx;
        const float bi = bih[h]         + bhh[h];
        const float bf = bih[H_ + h]    + bhh[H_ + h];
        const float bg = bih[2*H_ + h]  + bhh[2*H_ + h];
        const float bo = bih[3*H_ + h]  + bhh[3*H_ + h];
        #pragma unroll
        for (int r = 0; r < 2; r++) {
            const int m = m0 + ty*2 + r;
            float a0 = acc[r][0] + comb[wtid][r*4 + 0];
            float a1 = acc[r][1] + comb[wtid][r*4 + 1];
            float a2 = acc[r][2] + comb[wtid][r*4 + 2];
            float a3 = acc[r][3] + comb[wtid][r*4 + 3];
            float ig = sigm(a0 + bi);
            float fg = sigm(a1 + bf);
            float gg = tanhf(a2 + bg);
            float og = sigm(a3 + bo);
            float cn = fg * c_prev[m*H_ + h] + ig * gg;
            c_out[m*H_ + h] = cn;
            h_out[m*H_ + h] = og * tanhf(cn);
        }
    }
}

// ---------------------------------------------------------------------------
// Head GEMM, in-block split-K. (R9, unchanged)
// ---------------------------------------------------------------------------
struct GemmBuf16 { float Xs[2][16][17]; float Ws[2][16][68]; };

__global__ void __launch_bounds__(512) k_head(
    const float* __restrict__ sh1, const float* __restrict__ cvec,
    const float* __restrict__ W1, const float* __restrict__ W2,
    const float* __restrict__ b1, const float* __restrict__ b2)
{
    __shared__ GemmBuf16 gbuf[2];
    __shared__ float comb[256][4];
    const int tid = threadIdx.x;
    const int widx = tid >> 8;
    const int wtid = tid & 255;
    GemmBuf16& g = gbuf[widx];
    const int tx = wtid & 15, ty = wtid >> 4;
    const int m0 = blockIdx.y * 16;
    const int n0 = blockIdx.x * 64;
    const int lkk = tx, lr = ty;
    const int nt = 8;                       // K=256, half=128

    const float* Xsrc = widx ? cvec : sh1;
    const float* Wsrc = widx ? W2 : W1;

    {
        int k = lkk;
        g.Xs[0][lkk][lr] = Xsrc[(m0+lr)*H_ + k];
        #pragma unroll
        for (int p = 0; p < 4; p++)
            g.Ws[0][lkk][lr + p*16] = Wsrc[(n0 + lr + p*16)*H_ + k];
    }
    __syncthreads();

    float acc[4] = {};
    for (int it = 0; it < nt; it++) {
        const int cur = it & 1, nxt = cur ^ 1;
        float px0 = 0.f, pw[4] = {0.f,0.f,0.f,0.f};
        const bool more = (it + 1 < nt);
        if (more) {
            int k = ((it + 1) * 16 + lkk) & 127;
            px0 = Xsrc[(m0+lr)*H_ + k];
            #pragma unroll
            for (int p = 0; p < 4; p++) pw[p] = Wsrc[(n0+lr+p*16)*H_ + k];
        }
        #pragma unroll
        for (int kk = 0; kk < 16; kk++) {
            float x0 = g.Xs[cur][kk][ty];
            float4 wv = *(const float4*)&g.Ws[cur][kk][tx*4];
            acc[0] = fmaf(x0, wv.x, acc[0]);
            acc[1] = fmaf(x0, wv.y, acc[1]);
            acc[2] = fmaf(x0, wv.z, acc[2]);
            acc[3] = fmaf(x0, wv.w, acc[3]);
        }
        if (more) {
            g.Xs[nxt][lkk][lr] = px0;
            #pragma unroll
            for (int p = 0; p < 4; p++) g.Ws[nxt][lkk][lr + p*16] = pw[p];
            __syncthreads();
        }
    }

    if (widx == 1) {
        #pragma unroll
        for (int j = 0; j < 4; j++) comb[wtid][j] = acc[j];
    }
    __syncthreads();
    if (widx == 0) {
        const int n = n0 + tx*4;
        const int m = m0 + ty;
        #pragma unroll
        for (int j = 0; j < 4; j++)
            g_pre[(size_t)m*H_ + n + j] = acc[j] + comb[wtid][j] + b1[n+j] + b2[n+j];
    }
}

// ---------------------------------------------------------------------------
// Fused attention, MLP-batched streaming. One block per batch row, 512 thr.
// Scores: 4 t per iteration (4 ldcs in flight, 4 interleaved shuffle chains).
// Context: 4 t per iteration, 4 independent accumulators.
// ---------------------------------------------------------------------------
__global__ void __launch_bounds__(512) k_attn(
    const float* __restrict__ hk, const float* __restrict__ hv,
    const float* __restrict__ q, const float* __restrict__ mask,
    float* __restrict__ c_out, float* __restrict__ att0)
{
    __shared__ float  sa[T_];
    __shared__ float4 sq[32];
    __shared__ float4 part[16][32];
    __shared__ float  red[512];
    const int b = blockIdx.x, tid = threadIdx.x;
    const int warp = tid >> 5, lane = tid & 31;

    if (tid < 32) sq[tid] = ((const float4*)(q + (size_t)b * H_))[tid];
    __syncthreads();
    const float4 qv = sq[lane];

    // Phase 1: scores, 4 rows per iteration.
    const float4* kbase = (const float4*)(hk + (size_t)b * (T_ * H_));
    {
        const int tbeg = warp * 128;
        for (int t0 = tbeg; t0 < tbeg + 128; t0 += 4) {
            float4 v0 = __ldcs(&kbase[(size_t)(t0+0) * 32 + lane]);
            float4 v1 = __ldcs(&kbase[(size_t)(t0+1) * 32 + lane]);
            float4 v2 = __ldcs(&kbase[(size_t)(t0+2) * 32 + lane]);
            float4 v3 = __ldcs(&kbase[(size_t)(t0+3) * 32 + lane]);
            float d0 = v0.x*qv.x + v0.y*qv.y + v0.z*qv.z + v0.w*qv.w;
            float d1 = v1.x*qv.x + v1.y*qv.y + v1.z*qv.z + v1.w*qv.w;
            float d2 = v2.x*qv.x + v2.y*qv.y + v2.z*qv.z + v2.w*qv.w;
            float d3 = v3.x*qv.x + v3.y*qv.y + v3.z*qv.z + v3.w*qv.w;
            #pragma unroll
            for (int st = 16; st > 0; st >>= 1) {
                d0 += __shfl_xor_sync(0xffffffffu, d0, st);
                d1 += __shfl_xor_sync(0xffffffffu, d1, st);
                d2 += __shfl_xor_sync(0xffffffffu, d2, st);
                d3 += __shfl_xor_sync(0xffffffffu, d3, st);
            }
            if (lane == 0) {
                sa[t0]   = d0;
                sa[t0+1] = d1;
                sa[t0+2] = d2;
                sa[t0+3] = d3;
            }
        }
    }
    __syncthreads();

    // Phase 2: masked, renormalized softmax (4 elems/thread)
    {
        const float* mk = mask + (size_t)b * T_;
        float loc[4];
        float mx = -1e30f;
        #pragma unroll
        for (int i = 0; i < 4; i++) { loc[i] = sa[tid + i*512]; mx = fmaxf(mx, loc[i]); }
        red[tid] = mx; __syncthreads();
        for (int st = 256; st > 0; st >>= 1) {
            if (tid < st) red[tid] = fmaxf(red[tid], red[tid + st]);
            __syncthreads();
        }
        mx = red[0]; __syncthreads();
        float sum = 0.f;
        #pragma unroll
        for (int i = 0; i < 4; i++) {
            float e = __expf(loc[i] - mx) * mk[tid + i*512];
            loc[i] = e; sum += e;
        }
        red[tid] = sum; __syncthreads();
        for (int st = 256; st > 0; st >>= 1) {
            if (tid < st) red[tid] += red[tid + st];
            __syncthreads();
        }
        const float inv = 1.f / red[0];
        #pragma unroll
        for (int i = 0; i < 4; i++) {
            float a = loc[i] * inv;
            sa[tid + i*512] = a;
            if (b == 0) att0[tid + i*512] = a;
        }
    }
    __syncthreads();

    // Phase 3: context, 4 rows per iteration, 4 accumulators.
    const float4* vbase = (const float4*)(hv + (size_t)b * (T_ * H_));
    float4 a0 = make_float4(0.f,0.f,0.f,0.f);
    float4 a1 = make_float4(0.f,0.f,0.f,0.f);
    float4 a2 = make_float4(0.f,0.f,0.f,0.f);
    float4 a3 = make_float4(0.f,0.f,0.f,0.f);
    for (int t = warp; t < T_; t += 64) {
        float w0 = sa[t], w1 = sa[t+16], w2 = sa[t+32], w3 = sa[t+48];
        float4 v0 = __ldcs(&vbase[(size_t)(t)    * 32 + lane]);
        float4 v1 = __ldcs(&vbase[(size_t)(t+16) * 32 + lane]);
        float4 v2 = __ldcs(&vbase[(size_t)(t+32) * 32 + lane]);
        float4 v3 = __ldcs(&vbase[(size_t)(t+48) * 32 + lane]);
        a0.x = fmaf(w0, v0.x, a0.x); a0.y = fmaf(w0, v0.y, a0.y);
        a0.z = fmaf(w0, v0.z, a0.z); a0.w = fmaf(w0, v0.w, a0.w);
        a1.x = fmaf(w1, v1.x, a1.x); a1.y = fmaf(w1, v1.y, a1.y);
        a1.z = fmaf(w1, v1.z, a1.z); a1.w = fmaf(w1, v1.w, a1.w);
        a2.x = fmaf(w2, v2.x, a2.x); a2.y = fmaf(w2, v2.y, a2.y);
        a2.z = fmaf(w2, v2.z, a2.z); a2.w = fmaf(w2, v2.w, a2.w);
        a3.x = fmaf(w3, v3.x, a3.x); a3.y = fmaf(w3, v3.y, a3.y);
        a3.z = fmaf(w3, v3.z, a3.z); a3.w = fmaf(w3, v3.w, a3.w);
    }
    a0.x += a1.x + a2.x + a3.x;
    a0.y += a1.y + a2.y + a3.y;
    a0.z += a1.z + a2.z + a3.z;
    a0.w += a1.w + a2.w + a3.w;
    part[warp][lane] = a0;
    __syncthreads();
    if (warp == 0) {
        float4 s = part[0][lane];
        #pragma unroll
        for (int w = 1; w < 16; w++) {
            float4 p = part[w][lane];
            s.x += p.x; s.y += p.y; s.z += p.z; s.w += p.w;
        }
        ((float4*)(c_out + (size_t)b * H_))[lane] = s;
    }
}

// ---------------------------------------------------------------------------
// BatchNorm training stats over batch (block per feature). (unchanged)
// ---------------------------------------------------------------------------
__global__ void k_bn(void) {
    int f = blockIdx.x, tid = threadIdx.x;
    float v0 = g_pre[(size_t)tid * H_ + f];
    float v1 = g_pre[(size_t)(tid + 256) * H_ + f];
    __shared__ float rs[256], rq[256];
    rs[tid] = v0 + v1;
    rq[tid] = v0 * v0 + v1 * v1;
    __syncthreads();
    for (int st = 128; st > 0; st >>= 1) {
        if (tid < st) { rs[tid] += rs[tid + st]; rq[tid] += rq[tid + st]; }
        __syncthreads();
    }
    if (tid == 0) {
        float mn = rs[0] * (1.f / 512.f);
        g_mean[f] = mn;
        g_var[f] = rq[0] * (1.f / 512.f) - mn * mn;
    }
}

// ---------------------------------------------------------------------------
// BN apply + ReLU + final linear (warp-per-output GEMV). (unchanged)
// ---------------------------------------------------------------------------
__global__ void k_final(const float* __restrict__ gamma, const float* __restrict__ beta,
                        const float* __restrict__ W3, const float* __restrict__ b3,
                        float* __restrict__ out) {
    int b = blockIdx.x, f = threadIdx.x;
    const int warp = f >> 5, lane = f & 31;
    __shared__ float sn[H_];
    float v = g_pre[(size_t)b * H_ + f];
    float n = (v - g_mean[f]) * rsqrtf(g_var[f] + 1e-5f) * gamma[f] + beta[f];
    sn[f] = fmaxf(n, 0.f);
    __syncthreads();
    float x0 = sn[lane], x1 = sn[lane + 32], x2 = sn[lane + 64], x3 = sn[lane + 96];
    for (int vo = warp; vo < V_; vo += 4) {
        const float* w = W3 + (size_t)vo * H_;
        float d = x0 * w[lane] + x1 * w[lane + 32] + x2 * w[lane + 64] + x3 * w[lane + 96];
        d += __shfl_xor_sync(0xffffffffu, d, 16);
        d += __shfl_xor_sync(0xffffffffu, d, 8);
        d += __shfl_xor_sync(0xffffffffu, d, 4);
        d += __shfl_xor_sync(0xffffffffu, d, 2);
        d += __shfl_xor_sync(0xffffffffu, d, 1);
        if (lane == 0) out[(size_t)b * V_ + vo] = d + b3[vo];
    }
}

// ---------------------------------------------------------------------------
extern "C" void kernel_launch(void* const* d_in, const int* in_sizes, int n_in,
                              void* d_out_v, int out_size) {
    const float* hk    = (const float*)d_in[0];
    const float* hv    = (const float*)d_in[1];
    const float* y_1   = (const float*)d_in[2];
    const float* c_1   = (const float*)d_in[3];
    const float* sh_1  = (const float*)d_in[4];   // [2,B,H]
    const float* sc_1  = (const float*)d_in[5];   // [2,B,H]
    const float* mask  = (const float*)d_in[6];
    const float* W_ih0 = (const float*)d_in[7];   // [512, 384]
    const float* W_hh0 = (const float*)d_in[8];   // [512, 128]
    const float* b_ih0 = (const float*)d_in[9];
    const float* b_hh0 = (const float*)d_in[10];
    const float* W_ih1 = (const float*)d_in[11];  // [512, 128]
    const float* W_hh1 = (const float*)d_in[12];  // [512, 128]
    const float* b_ih1 = (const float*)d_in[13];
    const float* b_hh1 = (const float*)d_in[14];
    const float* W1    = (const float*)d_in[15];  // [128, 128]
    const float* b1    = (const float*)d_in[16];
    const float* W2    = (const float*)d_in[17];  // [128, 128]
    const float* b2    = (const float*)d_in[18];
    const float* W3    = (const float*)d_in[19];  // [34, 128]
    const float* b3    = (const float*)d_in[20];
    const float* gamma = (const float*)d_in[21];
    const float* beta  = (const float*)d_in[22];
    float* d_out = (float*)d_out_v;
    (void)in_sizes; (void)n_in; (void)out_size;

    // LSTM cell 0: X = [y_1(256) | c_1(128) | sh_1[0](128)], Kin=384, K=512
    k_lstm<<<dim3(H_/16, B_/32), 512>>>(
        y_1, E_, c_1, H_, sh_1, H_,
        W_ih0, E_ + H_, W_hh0, b_ih0, b_hh0,
        sc_1, d_out + OFF_SH0, d_out + OFF_SC0);

    // LSTM cell 1: X = [sh0(128) | sh_1[1](128)], Kin=128, K=256
    k_lstm<<<dim3(H_/16, B_/32), 512>>>(
        d_out + OFF_SH0, H_, sh_1 + B_*H_, H_, (const float*)nullptr, 0,
        W_ih1, H_, W_hh1, b_ih1, b_hh1,
        sc_1 + B_*H_, d_out + OFF_SH1, d_out + OFF_SC1);

    // Attention (fused scores + softmax + context, MLP-batched)
    k_attn<<<B_, 512>>>(hk, hv, d_out + OFF_SH1, mask,
                        d_out + OFF_C, d_out + OFF_ATT);

    // Head
    k_head<<<dim3(2, B_/16), 512>>>(d_out + OFF_SH1, d_out + OFF_C, W1, W2, b1, b2);
    k_bn<<<H_, 256>>>();
    k_final<<<B_, 128>>>(gamma, beta, W3, b3, d_out + OFF_OUT);
}

// round 11
// speedup vs baseline: 1.1863x; 1.0147x over previous
#include <cuda_runtime.h>
#include <math.h>

// Problem constants
#define B_ 512
#define T_ 2048
#define H_ 128
#define E_ 256
#define V_ 34

// Output layout: (out[B,V], c[B,H], sh0[B,H], sh1[B,H], sc0[B,H], sc1[B,H], atten_vec[T])
#define OFF_OUT 0
#define OFF_C   (B_*V_)
#define OFF_SH0 (OFF_C   + B_*H_)
#define OFF_SH1 (OFF_SH0 + B_*H_)
#define OFF_SC0 (OFF_SH1 + B_*H_)
#define OFF_SC1 (OFF_SC0 + B_*H_)
#define OFF_ATT (OFF_SC1 + B_*H_)

// Scratch (__device__ globals; no allocations allowed)
__device__ float g_pre[B_*H_];   // head pre-BN output
__device__ float g_mean[H_];
__device__ float g_var[H_];

__device__ __forceinline__ float sigm(float x) { return 1.f / (1.f + __expf(-x)); }

// ---------------------------------------------------------------------------
// LSTM cell with in-block split-K on the proven 32-row tile. (R9/R10, unchanged)
// ---------------------------------------------------------------------------
struct GemmBuf32 { float Xs[2][16][34]; float Ws[2][16][68]; };

__global__ void __launch_bounds__(512) k_lstm(
    const float* __restrict__ A, int ka,
    const float* __restrict__ Bp, int kb,
    const float* __restrict__ Cp, int kc,
    const float* __restrict__ Wih, int Kin,
    const float* __restrict__ Whh,
    const float* __restrict__ bih, const float* __restrict__ bhh,
    const float* __restrict__ c_prev,
    float* __restrict__ h_out, float* __restrict__ c_out)
{
    __shared__ GemmBuf32 gbuf[2];
    __shared__ float comb[256][8];
    const int tid = threadIdx.x;
    const int widx = tid >> 8;          // worker 0/1
    const int wtid = tid & 255;
    GemmBuf32& g = gbuf[widx];
    const int tx = wtid & 15, ty = wtid >> 4;
    const int m0 = blockIdx.y * 32;
    const int h0 = blockIdx.x * 16;
    const int lkk = wtid & 15, lr = wtid >> 4;

    const int K = ka + kb + kc;
    const int halfK = K >> 1;
    const int nt = halfK >> 4;
    const int kofs = widx * halfK;

    int wn[4];
    #pragma unroll
    for (int p = 0; p < 4; p++) {
        int c = lr + p * 16;
        wn[p] = (c & 3) * H_ + h0 + (c >> 2);   // gate*H + h
    }

    {
        int k = kofs + lkk;
        float x0, x1;
        if (k < ka)           { x0 = A[(m0+lr)*ka + k];            x1 = A[(m0+lr+16)*ka + k]; }
        else if (k < ka + kb) { x0 = Bp[(m0+lr)*kb + k - ka];      x1 = Bp[(m0+lr+16)*kb + k - ka]; }
        else                  { x0 = Cp[(m0+lr)*kc + k - ka - kb]; x1 = Cp[(m0+lr+16)*kc + k - ka - kb]; }
        g.Xs[0][lkk][lr] = x0; g.Xs[0][lkk][lr+16] = x1;
        #pragma unroll
        for (int p = 0; p < 4; p++)
            g.Ws[0][lkk][lr + p*16] = (k < Kin) ? Wih[wn[p]*Kin + k] : Whh[wn[p]*H_ + k - Kin];
    }
    __syncthreads();

    float acc[2][4] = {};
    for (int it = 0; it < nt; it++) {
        const int cur = it & 1, nxt = cur ^ 1;
        float px0 = 0.f, px1 = 0.f, pw[4] = {0.f,0.f,0.f,0.f};
        const bool more = (it + 1 < nt);
        if (more) {
            int k = kofs + (it + 1) * 16 + lkk;
            if (k < ka)           { px0 = A[(m0+lr)*ka + k];            px1 = A[(m0+lr+16)*ka + k]; }
            else if (k < ka + kb) { px0 = Bp[(m0+lr)*kb + k - ka];      px1 = Bp[(m0+lr+16)*kb + k - ka]; }
            else                  { px0 = Cp[(m0+lr)*kc + k - ka - kb]; px1 = Cp[(m0+lr+16)*kc + k - ka - kb]; }
            #pragma unroll
            for (int p = 0; p < 4; p++)
                pw[p] = (k < Kin) ? Wih[wn[p]*Kin + k] : Whh[wn[p]*H_ + k - Kin];
        }
        #pragma unroll
        for (int kk = 0; kk < 16; kk++) {
            float x0 = g.Xs[cur][kk][ty*2];
            float x1 = g.Xs[cur][kk][ty*2 + 1];
            float4 wv = *(const float4*)&g.Ws[cur][kk][tx*4];
            acc[0][0] = fmaf(x0, wv.x, acc[0][0]);
            acc[0][1] = fmaf(x0, wv.y, acc[0][1]);
            acc[0][2] = fmaf(x0, wv.z, acc[0][2]);
            acc[0][3] = fmaf(x0, wv.w, acc[0][3]);
            acc[1][0] = fmaf(x1, wv.x, acc[1][0]);
            acc[1][1] = fmaf(x1, wv.y, acc[1][1]);
            acc[1][2] = fmaf(x1, wv.z, acc[1][2]);
            acc[1][3] = fmaf(x1, wv.w, acc[1][3]);
        }
        if (more) {
            g.Xs[nxt][lkk][lr] = px0;
            g.Xs[nxt][lkk][lr+16] = px1;
            #pragma unroll
            for (int p = 0; p < 4; p++) g.Ws[nxt][lkk][lr + p*16] = pw[p];
            __syncthreads();
        }
    }

    if (widx == 1) {
        #pragma unroll
        for (int r = 0; r < 2; r++)
            #pragma unroll
            for (int j = 0; j < 4; j++) comb[wtid][r*4 + j] = acc[r][j];
    }
    __syncthreads();
    if (widx == 0) {
        const int h = h0 + tx;
        const float bi = bih[h]         + bhh[h];
        const float bf = bih[H_ + h]    + bhh[H_ + h];
        const float bg = bih[2*H_ + h]  + bhh[2*H_ + h];
        const float bo = bih[3*H_ + h]  + bhh[3*H_ + h];
        #pragma unroll
        for (int r = 0; r < 2; r++) {
            const int m = m0 + ty*2 + r;
            float a0 = acc[r][0] + comb[wtid][r*4 + 0];
            float a1 = acc[r][1] + comb[wtid][r*4 + 1];
            float a2 = acc[r][2] + comb[wtid][r*4 + 2];
            float a3 = acc[r][3] + comb[wtid][r*4 + 3];
            float ig = sigm(a0 + bi);
            float fg = sigm(a1 + bf);
            float gg = tanhf(a2 + bg);
            float og = sigm(a3 + bo);
            float cn = fg * c_prev[m*H_ + h] + ig * gg;
            c_out[m*H_ + h] = cn;
            h_out[m*H_ + h] = og * tanhf(cn);
        }
    }
}

// ---------------------------------------------------------------------------
// Fused attention + head: scores + masked renormalized softmax + context +
// head GEMM row (pre = q.W1^T + c.W2^T + b1 + b2), one block per batch row.
// 512 threads (16 warps). hk/hv streamed once with MLP=8 / MLP=4.
// ---------------------------------------------------------------------------
__global__ void __launch_bounds__(512) k_attn(
    const float* __restrict__ hk, const float* __restrict__ hv,
    const float* __restrict__ q, const float* __restrict__ mask,
    const float* __restrict__ W1, const float* __restrict__ W2,
    const float* __restrict__ b1, const float* __restrict__ b2,
    float* __restrict__ c_out, float* __restrict__ att0)
{
    __shared__ float  sa[T_];
    __shared__ float4 sq[32];           // q row (128 floats)
    __shared__ float4 cc[32];           // c row (128 floats)
    __shared__ float4 part[16][32];
    __shared__ float  red[16];
    const int b = blockIdx.x, tid = threadIdx.x;
    const int warp = tid >> 5, lane = tid & 31;

    if (tid < 32) sq[tid] = ((const float4*)(q + (size_t)b * H_))[tid];
    __syncthreads();
    const float4 qv = sq[lane];

    // ---- Phase 1: scores, 8 rows per iteration (MLP=8).
    const float4* kbase = (const float4*)(hk + (size_t)b * (T_ * H_));
    {
        const int tbeg = warp * 128;
        for (int t0 = tbeg; t0 < tbeg + 128; t0 += 8) {
            float4 v[8];
            #pragma unroll
            for (int j = 0; j < 8; j++)
                v[j] = __ldcs(&kbase[(size_t)(t0+j) * 32 + lane]);
            float d[8];
            #pragma unroll
            for (int j = 0; j < 8; j++)
                d[j] = v[j].x*qv.x + v[j].y*qv.y + v[j].z*qv.z + v[j].w*qv.w;
            #pragma unroll
            for (int st = 16; st > 0; st >>= 1) {
                #pragma unroll
                for (int j = 0; j < 8; j++)
                    d[j] += __shfl_xor_sync(0xffffffffu, d[j], st);
            }
            if (lane == 0) {
                #pragma unroll
                for (int j = 0; j < 8; j++) sa[t0+j] = d[j];
            }
        }
    }
    __syncthreads();

    // ---- Phase 2: masked renormalized softmax, warp-shuffle two-stage.
    {
        const float* mk = mask + (size_t)b * T_;
        float loc[4];
        float mx = -1e30f;
        #pragma unroll
        for (int i = 0; i < 4; i++) { loc[i] = sa[tid + i*512]; mx = fmaxf(mx, loc[i]); }
        #pragma unroll
        for (int st = 16; st > 0; st >>= 1)
            mx = fmaxf(mx, __shfl_xor_sync(0xffffffffu, mx, st));
        if (lane == 0) red[warp] = mx;
        __syncthreads();
        if (warp == 0) {
            float m2 = (lane < 16) ? red[lane] : -1e30f;
            #pragma unroll
            for (int st = 8; st > 0; st >>= 1)
                m2 = fmaxf(m2, __shfl_xor_sync(0xffffffffu, m2, st));
            if (lane == 0) red[0] = m2;
        }
        __syncthreads();
        mx = red[0];
        __syncthreads();                 // all reads of red[0] done before reuse

        float sum = 0.f;
        #pragma unroll
        for (int i = 0; i < 4; i++) {
            float e = __expf(loc[i] - mx) * mk[tid + i*512];
            loc[i] = e; sum += e;
        }
        #pragma unroll
        for (int st = 16; st > 0; st >>= 1)
            sum += __shfl_xor_sync(0xffffffffu, sum, st);
        if (lane == 0) red[warp] = sum;
        __syncthreads();
        if (warp == 0) {
            float s2 = (lane < 16) ? red[lane] : 0.f;
            #pragma unroll
            for (int st = 8; st > 0; st >>= 1)
                s2 += __shfl_xor_sync(0xffffffffu, s2, st);
            if (lane == 0) red[0] = s2;
        }
        __syncthreads();
        const float inv = 1.f / red[0];
        #pragma unroll
        for (int i = 0; i < 4; i++) {
            float a = loc[i] * inv;
            sa[tid + i*512] = a;
            if (b == 0) att0[tid + i*512] = a;
        }
    }
    __syncthreads();

    // ---- Phase 3: context, 4 rows per iteration, 4 accumulators.
    const float4* vbase = (const float4*)(hv + (size_t)b * (T_ * H_));
    float4 a0 = make_float4(0.f,0.f,0.f,0.f);
    float4 a1 = make_float4(0.f,0.f,0.f,0.f);
    float4 a2 = make_float4(0.f,0.f,0.f,0.f);
    float4 a3 = make_float4(0.f,0.f,0.f,0.f);
    for (int t = warp; t < T_; t += 64) {
        float w0 = sa[t], w1 = sa[t+16], w2 = sa[t+32], w3 = sa[t+48];
        float4 v0 = __ldcs(&vbase[(size_t)(t)    * 32 + lane]);
        float4 v1 = __ldcs(&vbase[(size_t)(t+16) * 32 + lane]);
        float4 v2 = __ldcs(&vbase[(size_t)(t+32) * 32 + lane]);
        float4 v3 = __ldcs(&vbase[(size_t)(t+48) * 32 + lane]);
        a0.x = fmaf(w0, v0.x, a0.x); a0.y = fmaf(w0, v0.y, a0.y);
        a0.z = fmaf(w0, v0.z, a0.z); a0.w = fmaf(w0, v0.w, a0.w);
        a1.x = fmaf(w1, v1.x, a1.x); a1.y = fmaf(w1, v1.y, a1.y);
        a1.z = fmaf(w1, v1.z, a1.z); a1.w = fmaf(w1, v1.w, a1.w);
        a2.x = fmaf(w2, v2.x, a2.x); a2.y = fmaf(w2, v2.y, a2.y);
        a2.z = fmaf(w2, v2.z, a2.z); a2.w = fmaf(w2, v2.w, a2.w);
        a3.x = fmaf(w3, v3.x, a3.x); a3.y = fmaf(w3, v3.y, a3.y);
        a3.z = fmaf(w3, v3.z, a3.z); a3.w = fmaf(w3, v3.w, a3.w);
    }
    a0.x += a1.x + a2.x + a3.x;
    a0.y += a1.y + a2.y + a3.y;
    a0.z += a1.z + a2.z + a3.z;
    a0.w += a1.w + a2.w + a3.w;
    part[warp][lane] = a0;
    __syncthreads();
    if (warp == 0) {
        float4 s = part[0][lane];
        #pragma unroll
        for (int w = 1; w < 16; w++) {
            float4 p = part[w][lane];
            s.x += p.x; s.y += p.y; s.z += p.z; s.w += p.w;
        }
        ((float4*)(c_out + (size_t)b * H_))[lane] = s;
        cc[lane] = s;
    }
    __syncthreads();

    // ---- Phase 4: head row. pre[b][n] = q.W1[n] + c.W2[n] + b1[n] + b2[n].
    // Warp w computes n = w*8 .. w*8+7; lane covers k-chunk 4*lane..4*lane+3.
    {
        const float4 xq = sq[lane];
        const float4 xc = cc[lane];
        #pragma unroll
        for (int j = 0; j < 8; j++) {
            const int n = warp * 8 + j;
            float4 w1v = __ldg(((const float4*)(W1 + (size_t)n * H_)) + lane);
            float4 w2v = __ldg(((const float4*)(W2 + (size_t)n * H_)) + lane);
            float d = xq.x*w1v.x + xq.y*w1v.y + xq.z*w1v.z + xq.w*w1v.w
                    + xc.x*w2v.x + xc.y*w2v.y + xc.z*w2v.z + xc.w*w2v.w;
            #pragma unroll
            for (int st = 16; st > 0; st >>= 1)
                d += __shfl_xor_sync(0xffffffffu, d, st);
            if (lane == 0)
                g_pre[(size_t)b * H_ + n] = d + b1[n] + b2[n];
        }
    }
}

// ---------------------------------------------------------------------------
// BatchNorm training stats over batch (block per feature). (unchanged)
// ---------------------------------------------------------------------------
__global__ void k_bn(void) {
    int f = blockIdx.x, tid = threadIdx.x;
    float v0 = g_pre[(size_t)tid * H_ + f];
    float v1 = g_pre[(size_t)(tid + 256) * H_ + f];
    __shared__ float rs[256], rq[256];
    rs[tid] = v0 + v1;
    rq[tid] = v0 * v0 + v1 * v1;
    __syncthreads();
    for (int st = 128; st > 0; st >>= 1) {
        if (tid < st) { rs[tid] += rs[tid + st]; rq[tid] += rq[tid + st]; }
        __syncthreads();
    }
    if (tid == 0) {
        float mn = rs[0] * (1.f / 512.f);
        g_mean[f] = mn;
        g_var[f] = rq[0] * (1.f / 512.f) - mn * mn;
    }
}

// ---------------------------------------------------------------------------
// BN apply + ReLU + final linear (warp-per-output GEMV). (unchanged)
// ---------------------------------------------------------------------------
__global__ void k_final(const float* __restrict__ gamma, const float* __restrict__ beta,
                        const float* __restrict__ W3, const float* __restrict__ b3,
                        float* __restrict__ out) {
    int b = blockIdx.x, f = threadIdx.x;
    const int warp = f >> 5, lane = f & 31;
    __shared__ float sn[H_];
    float v = g_pre[(size_t)b * H_ + f];
    float n = (v - g_mean[f]) * rsqrtf(g_var[f] + 1e-5f) * gamma[f] + beta[f];
    sn[f] = fmaxf(n, 0.f);
    __syncthreads();
    float x0 = sn[lane], x1 = sn[lane + 32], x2 = sn[lane + 64], x3 = sn[lane + 96];
    for (int vo = warp; vo < V_; vo += 4) {
        const float* w = W3 + (size_t)vo * H_;
        float d = x0 * w[lane] + x1 * w[lane + 32] + x2 * w[lane + 64] + x3 * w[lane + 96];
        d += __shfl_xor_sync(0xffffffffu, d, 16);
        d += __shfl_xor_sync(0xffffffffu, d, 8);
        d += __shfl_xor_sync(0xffffffffu, d, 4);
        d += __shfl_xor_sync(0xffffffffu, d, 2);
        d += __shfl_xor_sync(0xffffffffu, d, 1);
        if (lane == 0) out[(size_t)b * V_ + vo] = d + b3[vo];
    }
}

// ---------------------------------------------------------------------------
extern "C" void kernel_launch(void* const* d_in, const int* in_sizes, int n_in,
                              void* d_out_v, int out_size) {
    const float* hk    = (const float*)d_in[0];
    const float* hv    = (const float*)d_in[1];
    const float* y_1   = (const float*)d_in[2];
    const float* c_1   = (const float*)d_in[3];
    const float* sh_1  = (const float*)d_in[4];   // [2,B,H]
    const float* sc_1  = (const float*)d_in[5];   // [2,B,H]
    const float* mask  = (const float*)d_in[6];
    const float* W_ih0 = (const float*)d_in[7];   // [512, 384]
    const float* W_hh0 = (const float*)d_in[8];   // [512, 128]
    const float* b_ih0 = (const float*)d_in[9];
    const float* b_hh0 = (const float*)d_in[10];
    const float* W_ih1 = (const float*)d_in[11];  // [512, 128]
    const float* W_hh1 = (const float*)d_in[12];  // [512, 128]
    const float* b_ih1 = (const float*)d_in[13];
    const float* b_hh1 = (const float*)d_in[14];
    const float* W1    = (const float*)d_in[15];  // [128, 128]
    const float* b1    = (const float*)d_in[16];
    const float* W2    = (const float*)d_in[17];  // [128, 128]
    const float* b2    = (const float*)d_in[18];
    const float* W3    = (const float*)d_in[19];  // [34, 128]
    const float* b3    = (const float*)d_in[20];
    const float* gamma = (const float*)d_in[21];
    const float* beta  = (const float*)d_in[22];
    float* d_out = (float*)d_out_v;
    (void)in_sizes; (void)n_in; (void)out_size;

    // LSTM cell 0: X = [y_1(256) | c_1(128) | sh_1[0](128)], Kin=384, K=512
    k_lstm<<<dim3(H_/16, B_/32), 512>>>(
        y_1, E_, c_1, H_, sh_1, H_,
        W_ih0, E_ + H_, W_hh0, b_ih0, b_hh0,
        sc_1, d_out + OFF_SH0, d_out + OFF_SC0);

    // LSTM cell 1: X = [sh0(128) | sh_1[1](128)], Kin=128, K=256
    k_lstm<<<dim3(H_/16, B_/32), 512>>>(
        d_out + OFF_SH0, H_, sh_1 + B_*H_, H_, (const float*)nullptr, 0,
        W_ih1, H_, W_hh1, b_ih1, b_hh1,
        sc_1 + B_*H_, d_out + OFF_SH1, d_out + OFF_SC1);

    // Attention + head row (fused scores + softmax + context + head GEMM)
    k_attn<<<B_, 512>>>(hk, hv, d_out + OFF_SH1, mask,
                        W1, W2, b1, b2,
                        d_out + OFF_C, d_out + OFF_ATT);

    // BN stats + final
    k_bn<<<H_, 256>>>();
    k_final<<<B_, 128>>>(gamma, beta, W3, b3, d_out + OFF_OUT);
}

// round 12
// speedup vs baseline: 1.2531x; 1.0562x over previous
#include <cuda_runtime.h>
#include <math.h>

// Problem constants
#define B_ 512
#define T_ 2048
#define H_ 128
#define E_ 256
#define V_ 34

// Output layout: (out[B,V], c[B,H], sh0[B,H], sh1[B,H], sc0[B,H], sc1[B,H], atten_vec[T])
#define OFF_OUT 0
#define OFF_C   (B_*V_)
#define OFF_SH0 (OFF_C   + B_*H_)
#define OFF_SH1 (OFF_SH0 + B_*H_)
#define OFF_SC0 (OFF_SH1 + B_*H_)
#define OFF_SC1 (OFF_SC0 + B_*H_)
#define OFF_ATT (OFF_SC1 + B_*H_)

// Scratch (__device__ globals; no allocations allowed)
__device__ float g_pre[B_*H_];   // head pre-BN output
__device__ float g_mean[H_];
__device__ float g_var[H_];

__device__ __forceinline__ float sigm(float x) { return 1.f / (1.f + __expf(-x)); }

// ---------------------------------------------------------------------------
// LSTM cell with in-block split-K on the proven 32-row tile. (unchanged)
// ---------------------------------------------------------------------------
struct GemmBuf32 { float Xs[2][16][34]; float Ws[2][16][68]; };

__global__ void __launch_bounds__(512) k_lstm(
    const float* __restrict__ A, int ka,
    const float* __restrict__ Bp, int kb,
    const float* __restrict__ Cp, int kc,
    const float* __restrict__ Wih, int Kin,
    const float* __restrict__ Whh,
    const float* __restrict__ bih, const float* __restrict__ bhh,
    const float* __restrict__ c_prev,
    float* __restrict__ h_out, float* __restrict__ c_out)
{
    __shared__ GemmBuf32 gbuf[2];
    __shared__ float comb[256][8];
    const int tid = threadIdx.x;
    const int widx = tid >> 8;          // worker 0/1
    const int wtid = tid & 255;
    GemmBuf32& g = gbuf[widx];
    const int tx = wtid & 15, ty = wtid >> 4;
    const int m0 = blockIdx.y * 32;
    const int h0 = blockIdx.x * 16;
    const int lkk = wtid & 15, lr = wtid >> 4;

    const int K = ka + kb + kc;
    const int halfK = K >> 1;
    const int nt = halfK >> 4;
    const int kofs = widx * halfK;

    int wn[4];
    #pragma unroll
    for (int p = 0; p < 4; p++) {
        int c = lr + p * 16;
        wn[p] = (c & 3) * H_ + h0 + (c >> 2);   // gate*H + h
    }

    {
        int k = kofs + lkk;
        float x0, x1;
        if (k < ka)           { x0 = A[(m0+lr)*ka + k];            x1 = A[(m0+lr+16)*ka + k]; }
        else if (k < ka + kb) { x0 = Bp[(m0+lr)*kb + k - ka];      x1 = Bp[(m0+lr+16)*kb + k - ka]; }
        else                  { x0 = Cp[(m0+lr)*kc + k - ka - kb]; x1 = Cp[(m0+lr+16)*kc + k - ka - kb]; }
        g.Xs[0][lkk][lr] = x0; g.Xs[0][lkk][lr+16] = x1;
        #pragma unroll
        for (int p = 0; p < 4; p++)
            g.Ws[0][lkk][lr + p*16] = (k < Kin) ? Wih[wn[p]*Kin + k] : Whh[wn[p]*H_ + k - Kin];
    }
    __syncthreads();

    float acc[2][4] = {};
    for (int it = 0; it < nt; it++) {
        const int cur = it & 1, nxt = cur ^ 1;
        float px0 = 0.f, px1 = 0.f, pw[4] = {0.f,0.f,0.f,0.f};
        const bool more = (it + 1 < nt);
        if (more) {
            int k = kofs + (it + 1) * 16 + lkk;
            if (k < ka)           { px0 = A[(m0+lr)*ka + k];            px1 = A[(m0+lr+16)*ka + k]; }
            else if (k < ka + kb) { px0 = Bp[(m0+lr)*kb + k - ka];      px1 = Bp[(m0+lr+16)*kb + k - ka]; }
            else                  { px0 = Cp[(m0+lr)*kc + k - ka - kb]; px1 = Cp[(m0+lr+16)*kc + k - ka - kb]; }
            #pragma unroll
            for (int p = 0; p < 4; p++)
                pw[p] = (k < Kin) ? Wih[wn[p]*Kin + k] : Whh[wn[p]*H_ + k - Kin];
        }
        #pragma unroll
        for (int kk = 0; kk < 16; kk++) {
            float x0 = g.Xs[cur][kk][ty*2];
            float x1 = g.Xs[cur][kk][ty*2 + 1];
            float4 wv = *(const float4*)&g.Ws[cur][kk][tx*4];
            acc[0][0] = fmaf(x0, wv.x, acc[0][0]);
            acc[0][1] = fmaf(x0, wv.y, acc[0][1]);
            acc[0][2] = fmaf(x0, wv.z, acc[0][2]);
            acc[0][3] = fmaf(x0, wv.w, acc[0][3]);
            acc[1][0] = fmaf(x1, wv.x, acc[1][0]);
            acc[1][1] = fmaf(x1, wv.y, acc[1][1]);
            acc[1][2] = fmaf(x1, wv.z, acc[1][2]);
            acc[1][3] = fmaf(x1, wv.w, acc[1][3]);
        }
        if (more) {
            g.Xs[nxt][lkk][lr] = px0;
            g.Xs[nxt][lkk][lr+16] = px1;
            #pragma unroll
            for (int p = 0; p < 4; p++) g.Ws[nxt][lkk][lr + p*16] = pw[p];
            __syncthreads();
        }
    }

    if (widx == 1) {
        #pragma unroll
        for (int r = 0; r < 2; r++)
            #pragma unroll
            for (int j = 0; j < 4; j++) comb[wtid][r*4 + j] = acc[r][j];
    }
    __syncthreads();
    if (widx == 0) {
        const int h = h0 + tx;
        const float bi = bih[h]         + bhh[h];
        const float bf = bih[H_ + h]    + bhh[H_ + h];
        const float bg = bih[2*H_ + h]  + bhh[2*H_ + h];
        const float bo = bih[3*H_ + h]  + bhh[3*H_ + h];
        #pragma unroll
        for (int r = 0; r < 2; r++) {
            const int m = m0 + ty*2 + r;
            float a0 = acc[r][0] + comb[wtid][r*4 + 0];
            float a1 = acc[r][1] + comb[wtid][r*4 + 1];
            float a2 = acc[r][2] + comb[wtid][r*4 + 2];
            float a3 = acc[r][3] + comb[wtid][r*4 + 3];
            float ig = sigm(a0 + bi);
            float fg = sigm(a1 + bf);
            float gg = tanhf(a2 + bg);
            float og = sigm(a3 + bo);
            float cn = fg * c_prev[m*H_ + h] + ig * gg;
            c_out[m*H_ + h] = cn;
            h_out[m*H_ + h] = og * tanhf(cn);
        }
    }
}

// ---------------------------------------------------------------------------
// Fused attention + head, 256-thread blocks (8 warps) for 4 resident
// blocks/SM (reg-capped) -> better cross-block phase overlap.
// One block per batch row; hk/hv streamed once.
// ---------------------------------------------------------------------------
__global__ void __launch_bounds__(256, 4) k_attn(
    const float* __restrict__ hk, const float* __restrict__ hv,
    const float* __restrict__ q, const float* __restrict__ mask,
    const float* __restrict__ W1, const float* __restrict__ W2,
    const float* __restrict__ b1, const float* __restrict__ b2,
    float* __restrict__ c_out, float* __restrict__ att0)
{
    __shared__ float  sa[T_];
    __shared__ float4 sq[32];           // q row
    __shared__ float4 cc[32];           // c row
    __shared__ float4 part[8][32];
    __shared__ float  red[8];
    const int b = blockIdx.x, tid = threadIdx.x;
    const int warp = tid >> 5, lane = tid & 31;

    if (tid < 32) sq[tid] = ((const float4*)(q + (size_t)b * H_))[tid];
    __syncthreads();
    const float4 qv = sq[lane];

    // ---- Phase 1: scores. Warp w covers t in [w*256,(w+1)*256), MLP=8.
    const float4* kbase = (const float4*)(hk + (size_t)b * (T_ * H_));
    {
        const int tbeg = warp * 256;
        for (int t0 = tbeg; t0 < tbeg + 256; t0 += 8) {
            float4 v[8];
            #pragma unroll
            for (int j = 0; j < 8; j++)
                v[j] = __ldcs(&kbase[(size_t)(t0+j) * 32 + lane]);
            float d[8];
            #pragma unroll
            for (int j = 0; j < 8; j++)
                d[j] = v[j].x*qv.x + v[j].y*qv.y + v[j].z*qv.z + v[j].w*qv.w;
            #pragma unroll
            for (int st = 16; st > 0; st >>= 1) {
                #pragma unroll
                for (int j = 0; j < 8; j++)
                    d[j] += __shfl_xor_sync(0xffffffffu, d[j], st);
            }
            if (lane == 0) {
                #pragma unroll
                for (int j = 0; j < 8; j++) sa[t0+j] = d[j];
            }
        }
    }
    __syncthreads();

    // ---- Phase 2: masked renormalized softmax. 8 elems/thread, smem-resident
    // (no loc[] array -> low regs). Warp-shuffle two-stage reductions.
    {
        const float* mk = mask + (size_t)b * T_;
        float mx = -1e30f;
        #pragma unroll
        for (int i = 0; i < 8; i++) mx = fmaxf(mx, sa[tid + i*256]);
        #pragma unroll
        for (int st = 16; st > 0; st >>= 1)
            mx = fmaxf(mx, __shfl_xor_sync(0xffffffffu, mx, st));
        if (lane == 0) red[warp] = mx;
        __syncthreads();
        if (warp == 0) {
            float m2 = (lane < 8) ? red[lane] : -1e30f;
            #pragma unroll
            for (int st = 4; st > 0; st >>= 1)
                m2 = fmaxf(m2, __shfl_xor_sync(0xffffffffu, m2, st));
            if (lane == 0) red[0] = m2;
        }
        __syncthreads();
        mx = red[0];
        __syncthreads();

        float sum = 0.f;
        #pragma unroll
        for (int i = 0; i < 8; i++) {
            float e = __expf(sa[tid + i*256] - mx) * mk[tid + i*256];
            sa[tid + i*256] = e;
            sum += e;
        }
        #pragma unroll
        for (int st = 16; st > 0; st >>= 1)
            sum += __shfl_xor_sync(0xffffffffu, sum, st);
        if (lane == 0) red[warp] = sum;
        __syncthreads();
        if (warp == 0) {
            float s2 = (lane < 8) ? red[lane] : 0.f;
            #pragma unroll
            for (int st = 4; st > 0; st >>= 1)
                s2 += __shfl_xor_sync(0xffffffffu, s2, st);
            if (lane == 0) red[0] = s2;
        }
        __syncthreads();
        const float inv = 1.f / red[0];
        #pragma unroll
        for (int i = 0; i < 8; i++) {
            float a = sa[tid + i*256] * inv;
            sa[tid + i*256] = a;
            if (b == 0) att0[tid + i*256] = a;
        }
    }
    __syncthreads();

    // ---- Phase 3: context. Warp strides 8; MLP=4, 4 accumulators.
    const float4* vbase = (const float4*)(hv + (size_t)b * (T_ * H_));
    float4 a0 = make_float4(0.f,0.f,0.f,0.f);
    float4 a1 = make_float4(0.f,0.f,0.f,0.f);
    float4 a2 = make_float4(0.f,0.f,0.f,0.f);
    float4 a3 = make_float4(0.f,0.f,0.f,0.f);
    for (int t = warp; t < T_; t += 32) {
        float w0 = sa[t], w1 = sa[t+8], w2 = sa[t+16], w3 = sa[t+24];
        float4 v0 = __ldcs(&vbase[(size_t)(t)    * 32 + lane]);
        float4 v1 = __ldcs(&vbase[(size_t)(t+8)  * 32 + lane]);
        float4 v2 = __ldcs(&vbase[(size_t)(t+16) * 32 + lane]);
        float4 v3 = __ldcs(&vbase[(size_t)(t+24) * 32 + lane]);
        a0.x = fmaf(w0, v0.x, a0.x); a0.y = fmaf(w0, v0.y, a0.y);
        a0.z = fmaf(w0, v0.z, a0.z); a0.w = fmaf(w0, v0.w, a0.w);
        a1.x = fmaf(w1, v1.x, a1.x); a1.y = fmaf(w1, v1.y, a1.y);
        a1.z = fmaf(w1, v1.z, a1.z); a1.w = fmaf(w1, v1.w, a1.w);
        a2.x = fmaf(w2, v2.x, a2.x); a2.y = fmaf(w2, v2.y, a2.y);
        a2.z = fmaf(w2, v2.z, a2.z); a2.w = fmaf(w2, v2.w, a2.w);
        a3.x = fmaf(w3, v3.x, a3.x); a3.y = fmaf(w3, v3.y, a3.y);
        a3.z = fmaf(w3, v3.z, a3.z); a3.w = fmaf(w3, v3.w, a3.w);
    }
    a0.x += a1.x + a2.x + a3.x;
    a0.y += a1.y + a2.y + a3.y;
    a0.z += a1.z + a2.z + a3.z;
    a0.w += a1.w + a2.w + a3.w;
    part[warp][lane] = a0;
    __syncthreads();
    if (warp == 0) {
        float4 s = part[0][lane];
        #pragma unroll
        for (int w = 1; w < 8; w++) {
            float4 p = part[w][lane];
            s.x += p.x; s.y += p.y; s.z += p.z; s.w += p.w;
        }
        ((float4*)(c_out + (size_t)b * H_))[lane] = s;
        cc[lane] = s;
    }
    __syncthreads();

    // ---- Phase 4: head row. Warp w computes n = w*16 .. w*16+15.
    {
        const float4 xq = sq[lane];
        const float4 xc = cc[lane];
        #pragma unroll
        for (int j = 0; j < 16; j++) {
            const int n = warp * 16 + j;
            float4 w1v = __ldg(((const float4*)(W1 + (size_t)n * H_)) + lane);
            float4 w2v = __ldg(((const float4*)(W2 + (size_t)n * H_)) + lane);
            float d = xq.x*w1v.x + xq.y*w1v.y + xq.z*w1v.z + xq.w*w1v.w
                    + xc.x*w2v.x + xc.y*w2v.y + xc.z*w2v.z + xc.w*w2v.w;
            #pragma unroll
            for (int st = 16; st > 0; st >>= 1)
                d += __shfl_xor_sync(0xffffffffu, d, st);
            if (lane == 0)
                g_pre[(size_t)b * H_ + n] = d + b1[n] + b2[n];
        }
    }
}

// ---------------------------------------------------------------------------
// BatchNorm training stats, coalesced: grid=4 blocks x 512 thr (16 warps).
// Block covers features f0..f0+31 (lane = feature). Warp w reads rows
// w, w+16, ... — one 128B line per row. 4 partials for MLP.
// ---------------------------------------------------------------------------
__global__ void __launch_bounds__(512) k_bn(void) {
    const int f0 = blockIdx.x * 32;
    const int tid = threadIdx.x;
    const int warp = tid >> 5, lane = tid & 31;
    float s0 = 0.f, s1 = 0.f, s2 = 0.f, s3 = 0.f;
    float q0 = 0.f, q1 = 0.f, q2 = 0.f, q3 = 0.f;
    for (int r = warp; r < B_; r += 64) {
        float v0 = g_pre[(size_t)(r)      * H_ + f0 + lane];
        float v1 = g_pre[(size_t)(r + 16) * H_ + f0 + lane];
        float v2 = g_pre[(size_t)(r + 32) * H_ + f0 + lane];
        float v3 = g_pre[(size_t)(r + 48) * H_ + f0 + lane];
        s0 += v0; q0 += v0*v0;
        s1 += v1; q1 += v1*v1;
        s2 += v2; q2 += v2*v2;
        s3 += v3; q3 += v3*v3;
    }
    __shared__ float ss[16][32], qq[16][32];
    ss[warp][lane] = (s0 + s1) + (s2 + s3);
    qq[warp][lane] = (q0 + q1) + (q2 + q3);
    __syncthreads();
    if (tid < 32) {
        float S = 0.f, Q = 0.f;
        #pragma unroll
        for (int w = 0; w < 16; w++) { S += ss[w][tid]; Q += qq[w][tid]; }
        float mn = S * (1.f / 512.f);
        g_mean[f0 + tid] = mn;
        g_var[f0 + tid] = Q * (1.f / 512.f) - mn * mn;
    }
}

// ---------------------------------------------------------------------------
// BN apply + ReLU + final linear (warp-per-output GEMV). (unchanged)
// ---------------------------------------------------------------------------
__global__ void k_final(const float* __restrict__ gamma, const float* __restrict__ beta,
                        const float* __restrict__ W3, const float* __restrict__ b3,
                        float* __restrict__ out) {
    int b = blockIdx.x, f = threadIdx.x;
    const int warp = f >> 5, lane = f & 31;
    __shared__ float sn[H_];
    float v = g_pre[(size_t)b * H_ + f];
    float n = (v - g_mean[f]) * rsqrtf(g_var[f] + 1e-5f) * gamma[f] + beta[f];
    sn[f] = fmaxf(n, 0.f);
    __syncthreads();
    float x0 = sn[lane], x1 = sn[lane + 32], x2 = sn[lane + 64], x3 = sn[lane + 96];
    for (int vo = warp; vo < V_; vo += 4) {
        const float* w = W3 + (size_t)vo * H_;
        float d = x0 * w[lane] + x1 * w[lane + 32] + x2 * w[lane + 64] + x3 * w[lane + 96];
        d += __shfl_xor_sync(0xffffffffu, d, 16);
        d += __shfl_xor_sync(0xffffffffu, d, 8);
        d += __shfl_xor_sync(0xffffffffu, d, 4);
        d += __shfl_xor_sync(0xffffffffu, d, 2);
        d += __shfl_xor_sync(0xffffffffu, d, 1);
        if (lane == 0) out[(size_t)b * V_ + vo] = d + b3[vo];
    }
}

// ---------------------------------------------------------------------------
extern "C" void kernel_launch(void* const* d_in, const int* in_sizes, int n_in,
                              void* d_out_v, int out_size) {
    const float* hk    = (const float*)d_in[0];
    const float* hv    = (const float*)d_in[1];
    const float* y_1   = (const float*)d_in[2];
    const float* c_1   = (const float*)d_in[3];
    const float* sh_1  = (const float*)d_in[4];   // [2,B,H]
    const float* sc_1  = (const float*)d_in[5];   // [2,B,H]
    const float* mask  = (const float*)d_in[6];
    const float* W_ih0 = (const float*)d_in[7];   // [512, 384]
    const float* W_hh0 = (const float*)d_in[8];   // [512, 128]
    const float* b_ih0 = (const float*)d_in[9];
    const float* b_hh0 = (const float*)d_in[10];
    const float* W_ih1 = (const float*)d_in[11];  // [512, 128]
    const float* W_hh1 = (const float*)d_in[12];  // [512, 128]
    const float* b_ih1 = (const float*)d_in[13];
    const float* b_hh1 = (const float*)d_in[14];
    const float* W1    = (const float*)d_in[15];  // [128, 128]
    const float* b1    = (const float*)d_in[16];
    const float* W2    = (const float*)d_in[17];  // [128, 128]
    const float* b2    = (const float*)d_in[18];
    const float* W3    = (const float*)d_in[19];  // [34, 128]
    const float* b3    = (const float*)d_in[20];
    const float* gamma = (const float*)d_in[21];
    const float* beta  = (const float*)d_in[22];
    float* d_out = (float*)d_out_v;
    (void)in_sizes; (void)n_in; (void)out_size;

    // LSTM cell 0: X = [y_1(256) | c_1(128) | sh_1[0](128)], Kin=384, K=512
    k_lstm<<<dim3(H_/16, B_/32), 512>>>(
        y_1, E_, c_1, H_, sh_1, H_,
        W_ih0, E_ + H_, W_hh0, b_ih0, b_hh0,
        sc_1, d_out + OFF_SH0, d_out + OFF_SC0);

    // LSTM cell 1: X = [sh0(128) | sh_1[1](128)], Kin=128, K=256
    k_lstm<<<dim3(H_/16, B_/32), 512>>>(
        d_out + OFF_SH0, H_, sh_1 + B_*H_, H_, (const float*)nullptr, 0,
        W_ih1, H_, W_hh1, b_ih1, b_hh1,
        sc_1 + B_*H_, d_out + OFF_SH1, d_out + OFF_SC1);

    // Attention + head row (256-thr blocks, 4 resident/SM)
    k_attn<<<B_, 256>>>(hk, hv, d_out + OFF_SH1, mask,
                        W1, W2, b1, b2,
                        d_out + OFF_C, d_out + OFF_ATT);

    // BN stats (coalesced) + final
    k_bn<<<4, 512>>>();
    k_final<<<B_, 128>>>(gamma, beta, W3, b3, d_out + OFF_OUT);
}